// round 9
// baseline (speedup 1.0000x reference)
#include <cuda_runtime.h>

#define N_NODES  50000
#define N_EDGES  800000
#define N_GRAPHS 128
#define D        128

// Scratch (device globals — no allocation allowed)
__device__ float g_hw[N_NODES * D];     // H @ W (layer1: unscaled; layer2: *dinv)
__device__ float g_agg[N_NODES * D];    // aggregated layer output
__device__ float4 g_z[N_NODES];         // layer-3 folded features (3 used)
__device__ float4 g_zagg[N_NODES];      // aggregated layer-3 output
__device__ float g_dinv[N_NODES];
__device__ int   g_ecnt[N_NODES];       // zero-init; re-zeroed by scan each replay
__device__ int   g_off[N_NODES + 1];    // CSR offsets
__device__ int   g_cur[N_NODES];        // fill cursors
__device__ int   g_srcs[N_EDGES];       // src node ids, grouped by dst
__device__ float4 g_wfold[D];           // W3 @ Wlin rows (xyz used)
__device__ float4 g_bfold;              // b3 @ Wlin + blin

// ---------------------------------------------------------------------------
// Streams/events for fork-join inside CUDA-graph capture (created once;
// no device memory involved).
// ---------------------------------------------------------------------------
static cudaStream_t g_side_stream;
static cudaEvent_t  g_ev_fork, g_ev_join;
static struct StreamInit {
    StreamInit() {
        cudaStreamCreateWithFlags(&g_side_stream, cudaStreamNonBlocking);
        cudaEventCreateWithFlags(&g_ev_fork, cudaEventDisableTiming);
        cudaEventCreateWithFlags(&g_ev_join, cudaEventDisableTiming);
    }
} g_stream_init;

// ---------------------------------------------------------------------------
// Fold W3@Wlin (+ b3@Wlin+blin): 129 blocks x 32 threads, shfl reduce.
// ---------------------------------------------------------------------------
__global__ __launch_bounds__(32) void fold_kernel(const float* __restrict__ W3,
                                                  const float* __restrict__ b3,
                                                  const float* __restrict__ Wlin,
                                                  const float* __restrict__ blin) {
    const int r    = blockIdx.x;     // 0..127 rows, 128 = bias
    const int lane = threadIdx.x;
    float a0 = 0.f, a1 = 0.f, a2 = 0.f;
    const float* vec = (r < D) ? (W3 + r * D) : b3;
#pragma unroll
    for (int k = lane; k < D; k += 32) {
        float w = vec[k];
        a0 = fmaf(w, Wlin[k * 3 + 0], a0);
        a1 = fmaf(w, Wlin[k * 3 + 1], a1);
        a2 = fmaf(w, Wlin[k * 3 + 2], a2);
    }
#pragma unroll
    for (int m = 16; m > 0; m >>= 1) {
        a0 += __shfl_xor_sync(0xffffffff, a0, m);
        a1 += __shfl_xor_sync(0xffffffff, a1, m);
        a2 += __shfl_xor_sync(0xffffffff, a2, m);
    }
    if (lane == 0) {
        if (r < D) g_wfold[r] = make_float4(a0, a1, a2, 0.f);
        else       g_bfold   = make_float4(a0 + blin[0], a1 + blin[1], a2 + blin[2], 0.f);
    }
}

// ---------------------------------------------------------------------------
// CSR build: histogram -> scan (+dinv, +self-reset) -> fill
// ---------------------------------------------------------------------------
__global__ void hist_kernel(const int* __restrict__ ei, int E) {
    int e = blockIdx.x * blockDim.x + threadIdx.x;
    if (e < E) atomicAdd(&g_ecnt[ei[E + e]], 1);
}

__global__ void scan_kernel(int n) {
    __shared__ int part[1024];
    const int t = threadIdx.x;
    const int chunk = (n + 1023) / 1024;
    const int s = t * chunk;
    const int e = min(s + chunk, n);
    int sum = 0;
    for (int i = s; i < e; i++) sum += g_ecnt[i];
    part[t] = sum;
    __syncthreads();
    for (int d = 1; d < 1024; d <<= 1) {
        int v = (t >= d) ? part[t - d] : 0;
        __syncthreads();
        part[t] += v;
        __syncthreads();
    }
    int run = part[t] - sum;
    for (int i = s; i < e; i++) {
        int c = g_ecnt[i];
        g_ecnt[i] = 0;                        // reset for next replay
        g_off[i] = run;
        g_cur[i] = run;
        g_dinv[i] = rsqrtf((float)(c + 1));   // +1 self-loop
        run += c;
    }
    if (e == n && s < n) g_off[n] = run;
}

__global__ void fill_kernel(const int* __restrict__ ei, int E) {
    int e = blockIdx.x * blockDim.x + threadIdx.x;
    if (e >= E) return;
    int row = ei[e];
    int col = ei[E + e];
    int pos = atomicAdd(&g_cur[col], 1);
    g_srcs[pos] = row;
}

// ---------------------------------------------------------------------------
// packed f32x2 helpers
// ---------------------------------------------------------------------------
__device__ __forceinline__ unsigned long long bcast2(float v) {
    unsigned long long r;
    asm("mov.b64 %0, {%1, %1};" : "=l"(r) : "r"(__float_as_uint(v)));
    return r;
}
__device__ __forceinline__ void fma2(unsigned long long& acc,
                                     unsigned long long a,
                                     unsigned long long b) {
    asm("fma.rn.f32x2 %0, %1, %2, %0;" : "+l"(acc) : "l"(a), "l"(b));
}
__device__ __forceinline__ void mul2(unsigned long long& d,
                                     unsigned long long s) {
    asm("mul.rn.f32x2 %0, %0, %1;" : "+l"(d) : "l"(s));
}

// ---------------------------------------------------------------------------
// GEMM: OUT[r,:] = (act(H)[r,:] @ W) [* dinv[r] if SCALE]
// 128 threads, 64 rows/block, 8x8 per thread (R6 geometry, crossbar-balanced).
// ---------------------------------------------------------------------------
template <bool RELU, bool SCALE>
__global__ __launch_bounds__(128, 4) void gemm_kernel(const float* __restrict__ H,
                                                      const float* __restrict__ W,
                                                      float* __restrict__ OUT, int n) {
    __shared__ float sW[32 * D];   // 16KB (one k-chunk)
    __shared__ float sH[64 * D];   // 32KB

    const int tid  = threadIdx.x;
    const int row0 = blockIdx.x * 64;

#pragma unroll
    for (int i = 0; i < 16; i++) {
        int idx = (i * 128 + tid) * 4;
        int r   = row0 + (idx >> 7);
        float4 v;
        if (r < n) {
            v = *(const float4*)(H + r * D + (idx & 127));
            if (RELU) {
                v.x = fmaxf(v.x, 0.f); v.y = fmaxf(v.y, 0.f);
                v.z = fmaxf(v.z, 0.f); v.w = fmaxf(v.w, 0.f);
            }
        } else {
            v = make_float4(0.f, 0.f, 0.f, 0.f);
        }
        *(float4*)(sH + idx) = v;
    }

    const int tx = tid & 15;
    const int ty = tid >> 4;

    unsigned long long acc[8][4] = {};

#pragma unroll
    for (int kc = 0; kc < 4; kc++) {
        __syncthreads();
#pragma unroll
        for (int i = 0; i < 8; i++) {
            int idx = (i * 128 + tid) * 4;
            *(float4*)(sW + idx) = *(const float4*)(W + kc * 32 * D + idx);
        }
        __syncthreads();

#pragma unroll 2
        for (int k = 0; k < 32; k += 4) {
            const int hk = kc * 32 + k;
            float4 h[8];
#pragma unroll
            for (int r = 0; r < 8; r++)
                h[r] = *(float4*)(sH + (ty * 8 + r) * D + hk);

#pragma unroll
            for (int kk = 0; kk < 4; kk++) {
                const ulonglong2* wr = (const ulonglong2*)(sW + (k + kk) * D + tx * 8);
                ulonglong2 wa = wr[0];
                ulonglong2 wb = wr[1];
#pragma unroll
                for (int r = 0; r < 8; r++) {
                    float hv = (kk == 0) ? h[r].x : (kk == 1) ? h[r].y
                             : (kk == 2) ? h[r].z : h[r].w;
                    unsigned long long p = bcast2(hv);
                    fma2(acc[r][0], p, wa.x);
                    fma2(acc[r][1], p, wa.y);
                    fma2(acc[r][2], p, wb.x);
                    fma2(acc[r][3], p, wb.y);
                }
            }
        }
    }

    const int col = tx * 8;
#pragma unroll
    for (int i = 0; i < 8; i++) {
        int r = row0 + ty * 8 + i;
        if (r < n) {
            if (SCALE) {
                unsigned long long sp = bcast2(g_dinv[r]);
                mul2(acc[i][0], sp); mul2(acc[i][1], sp);
                mul2(acc[i][2], sp); mul2(acc[i][3], sp);
            }
            ulonglong2* o = (ulonglong2*)(OUT + r * D + col);
            o[0] = make_ulonglong2(acc[i][0], acc[i][1]);
            o[1] = make_ulonglong2(acc[i][2], acc[i][3]);
        }
    }
}

// ---------------------------------------------------------------------------
// Gather aggregation (warp per node, float4 per lane, MLP=8).
// SCALE_SRC=false: hw already * dinv[src]; pure adds.
// SCALE_SRC=true : hw unscaled; multiply each source row by dinv[src].
// agg[i] = dinv[i] * (dinv[i]*hw[i](or hw'[i]) + sum) + b
// ---------------------------------------------------------------------------
template <bool SCALE_SRC>
__global__ __launch_bounds__(256) void gather_kernel(const float* __restrict__ b, int n) {
    const int node = blockIdx.x * 8 + (threadIdx.x >> 5);
    const int lane = threadIdx.x & 31;
    if (node >= n) return;

    const float4* __restrict__ hw4 = (const float4*)g_hw;
    const float s = g_dinv[node];

    float4 self = hw4[node * 32 + lane];
    float4 acc;
    if (SCALE_SRC) {
        acc.x = self.x * s; acc.y = self.y * s;
        acc.z = self.z * s; acc.w = self.w * s;
    } else {
        acc = self;
    }

    const int off = g_off[node];
    const int deg = g_off[node + 1] - off;
    const int* __restrict__ src = g_srcs + off;

    int j = 0;
    for (; j + 4 <= deg; j += 4) {
        int s0 = src[j + 0], s1 = src[j + 1], s2 = src[j + 2], s3 = src[j + 3];
        float4 v0 = __ldg(hw4 + s0 * 32 + lane);
        float4 v1 = __ldg(hw4 + s1 * 32 + lane);
        float4 v2 = __ldg(hw4 + s2 * 32 + lane);
        float4 v3 = __ldg(hw4 + s3 * 32 + lane);
        if (SCALE_SRC) {
            float d0 = __ldg(g_dinv + s0), d1 = __ldg(g_dinv + s1);
            float d2 = __ldg(g_dinv + s2), d3 = __ldg(g_dinv + s3);
            acc.x = fmaf(v0.x, d0, acc.x); acc.y = fmaf(v0.y, d0, acc.y);
            acc.z = fmaf(v0.z, d0, acc.z); acc.w = fmaf(v0.w, d0, acc.w);
            acc.x = fmaf(v1.x, d1, acc.x); acc.y = fmaf(v1.y, d1, acc.y);
            acc.z = fmaf(v1.z, d1, acc.z); acc.w = fmaf(v1.w, d1, acc.w);
            acc.x = fmaf(v2.x, d2, acc.x); acc.y = fmaf(v2.y, d2, acc.y);
            acc.z = fmaf(v2.z, d2, acc.z); acc.w = fmaf(v2.w, d2, acc.w);
            acc.x = fmaf(v3.x, d3, acc.x); acc.y = fmaf(v3.y, d3, acc.y);
            acc.z = fmaf(v3.z, d3, acc.z); acc.w = fmaf(v3.w, d3, acc.w);
        } else {
            acc.x += (v0.x + v1.x) + (v2.x + v3.x);
            acc.y += (v0.y + v1.y) + (v2.y + v3.y);
            acc.z += (v0.z + v1.z) + (v2.z + v3.z);
            acc.w += (v0.w + v1.w) + (v2.w + v3.w);
        }
    }
    for (; j < deg; j++) {
        int sj = src[j];
        float4 v = __ldg(hw4 + sj * 32 + lane);
        if (SCALE_SRC) {
            float dj = __ldg(g_dinv + sj);
            acc.x = fmaf(v.x, dj, acc.x); acc.y = fmaf(v.y, dj, acc.y);
            acc.z = fmaf(v.z, dj, acc.z); acc.w = fmaf(v.w, dj, acc.w);
        } else {
            acc.x += v.x; acc.y += v.y; acc.z += v.z; acc.w += v.w;
        }
    }

    float4 bb = ((const float4*)b)[lane];
    float4 out;
    out.x = fmaf(acc.x, s, bb.x);
    out.y = fmaf(acc.y, s, bb.y);
    out.z = fmaf(acc.z, s, bb.z);
    out.w = fmaf(acc.w, s, bb.w);
    ((float4*)g_agg)[node * 32 + lane] = out;
}

// ---------------------------------------------------------------------------
// GEMM3 (folded): z[i] = dinv[i] * (relu(h2[i]) @ Wfold)
// ---------------------------------------------------------------------------
__global__ __launch_bounds__(256) void gemm3_kernel(const float* __restrict__ H, int n) {
    __shared__ float4 swf[D];
    const int tid  = threadIdx.x;
    if (tid < D) swf[tid] = g_wfold[tid];
    __syncthreads();

    const int node = blockIdx.x * 8 + (tid >> 5);
    const int lane = tid & 31;
    if (node >= n) return;

    float4 h = *(const float4*)(H + node * D + lane * 4);
    h.x = fmaxf(h.x, 0.f); h.y = fmaxf(h.y, 0.f);
    h.z = fmaxf(h.z, 0.f); h.w = fmaxf(h.w, 0.f);

    float4 w0 = swf[lane * 4 + 0];
    float4 w1 = swf[lane * 4 + 1];
    float4 w2 = swf[lane * 4 + 2];
    float4 w3 = swf[lane * 4 + 3];

    float a0 = h.x * w0.x + h.y * w1.x + h.z * w2.x + h.w * w3.x;
    float a1 = h.x * w0.y + h.y * w1.y + h.z * w2.y + h.w * w3.y;
    float a2 = h.x * w0.z + h.y * w1.z + h.z * w2.z + h.w * w3.z;

#pragma unroll
    for (int m = 16; m > 0; m >>= 1) {
        a0 += __shfl_xor_sync(0xffffffff, a0, m);
        a1 += __shfl_xor_sync(0xffffffff, a1, m);
        a2 += __shfl_xor_sync(0xffffffff, a2, m);
    }
    if (lane == 0) {
        float s = g_dinv[node];
        g_z[node] = make_float4(a0 * s, a1 * s, a2 * s, 0.f);
    }
}

// ---------------------------------------------------------------------------
// gather3: zagg[i] = dinv[i] * (z[i] + sum_in z[src])
// ---------------------------------------------------------------------------
__global__ __launch_bounds__(256) void gather3_kernel(int n) {
    const int node = blockIdx.x * blockDim.x + threadIdx.x;
    if (node >= n) return;

    float4 zv = g_z[node];
    float a0 = zv.x, a1 = zv.y, a2 = zv.z;

    const int off = g_off[node];
    const int deg = g_off[node + 1] - off;
    const int* __restrict__ src = g_srcs + off;

    int j = 0;
    for (; j + 4 <= deg; j += 4) {
        float4 v0 = __ldg(&g_z[src[j + 0]]);
        float4 v1 = __ldg(&g_z[src[j + 1]]);
        float4 v2 = __ldg(&g_z[src[j + 2]]);
        float4 v3 = __ldg(&g_z[src[j + 3]]);
        a0 += (v0.x + v1.x) + (v2.x + v3.x);
        a1 += (v0.y + v1.y) + (v2.y + v3.y);
        a2 += (v0.z + v1.z) + (v2.z + v3.z);
    }
    for (; j < deg; j++) {
        float4 v = __ldg(&g_z[src[j]]);
        a0 += v.x; a1 += v.y; a2 += v.z;
    }
    float s = g_dinv[node];
    g_zagg[node] = make_float4(a0 * s, a1 * s, a2 * s, 0.f);
}

// ---------------------------------------------------------------------------
// pool: out[g] = mean over batch-range of zagg + bfold   (1 warp per graph)
// ---------------------------------------------------------------------------
__global__ __launch_bounds__(32) void pool_kernel(const int* __restrict__ batch,
                                                  float* __restrict__ out, int n) {
    const int g = blockIdx.x;
    const int lane = threadIdx.x;

    int target = g + (lane & 1);
    int lo = 0, hi = n;
    while (lo < hi) {
        int m = (lo + hi) >> 1;
        if (batch[m] < target) lo = m + 1; else hi = m;
    }
    int start = __shfl_sync(0xffffffff, lo, 0);
    int end   = __shfl_sync(0xffffffff, lo, 1);

    float a0 = 0.f, a1 = 0.f, a2 = 0.f;
    for (int i = start + lane; i < end; i += 32) {
        float4 v = g_zagg[i];
        a0 += v.x; a1 += v.y; a2 += v.z;
    }
#pragma unroll
    for (int m = 16; m > 0; m >>= 1) {
        a0 += __shfl_xor_sync(0xffffffff, a0, m);
        a1 += __shfl_xor_sync(0xffffffff, a1, m);
        a2 += __shfl_xor_sync(0xffffffff, a2, m);
    }
    if (lane == 0) {
        float inv = 1.f / fmaxf((float)(end - start), 1.f);
        float4 bf = g_bfold;
        out[g * 3 + 0] = fmaf(a0, inv, bf.x);
        out[g * 3 + 1] = fmaf(a1, inv, bf.y);
        out[g * 3 + 2] = fmaf(a2, inv, bf.z);
    }
}

// ---------------------------------------------------------------------------
// launch (fork-join: CSR build overlaps GEMM1)
// ---------------------------------------------------------------------------
extern "C" void kernel_launch(void* const* d_in, const int* in_sizes, int n_in,
                              void* d_out, int out_size) {
    const float* x     = (const float*)d_in[0];
    const int*   ei    = (const int*)  d_in[1];
    const int*   batch = (const int*)  d_in[2];
    const float* W1    = (const float*)d_in[3];
    const float* b1    = (const float*)d_in[4];
    const float* W2    = (const float*)d_in[5];
    const float* b2    = (const float*)d_in[6];
    const float* W3    = (const float*)d_in[7];
    const float* b3    = (const float*)d_in[8];
    const float* Wlin  = (const float*)d_in[9];
    const float* blin  = (const float*)d_in[10];
    float* out = (float*)d_out;

    const int n = in_sizes[0] / D;   // 50000
    const int E = in_sizes[1] / 2;   // 800000

    float* hw_ptr;
    cudaGetSymbolAddress((void**)&hw_ptr, g_hw);
    float* agg_ptr;
    cudaGetSymbolAddress((void**)&agg_ptr, g_agg);

    const int gemm_blocks = (n + 63) / 64;
    const int gath_blocks = (n + 7) / 8;

    // fork: side stream builds CSR + fold while main stream runs GEMM1
    cudaEventRecord(g_ev_fork, 0);
    cudaStreamWaitEvent(g_side_stream, g_ev_fork, 0);

    hist_kernel<<<(E + 255) / 256, 256, 0, g_side_stream>>>(ei, E);
    scan_kernel<<<1, 1024, 0, g_side_stream>>>(n);
    fill_kernel<<<(E + 255) / 256, 256, 0, g_side_stream>>>(ei, E);
    fold_kernel<<<D + 1, 32, 0, g_side_stream>>>(W3, b3, Wlin, blin);
    cudaEventRecord(g_ev_join, g_side_stream);

    // main stream: GEMM1 (dinv-free; scaling moved to gather1)
    gemm_kernel<false, false><<<gemm_blocks, 128>>>(x, W1, hw_ptr, n);

    // join
    cudaStreamWaitEvent(0, g_ev_join, 0);

    // layer 1 aggregation (applies dinv[src] per edge)
    gather_kernel<true><<<gath_blocks, 256>>>(b1, n);

    // layer 2 (relu fused into GEMM load; dinv in epilogue)
    gemm_kernel<true, true><<<gemm_blocks, 128>>>(agg_ptr, W2, hw_ptr, n);
    gather_kernel<false><<<gath_blocks, 256>>>(b2, n);

    // layer 3 folded with head: [N,128] @ [128,3]
    gemm3_kernel<<<gath_blocks, 256>>>(agg_ptr, n);
    gather3_kernel<<<(n + 255) / 256, 256>>>(n);

    // mean pool + bias
    pool_kernel<<<N_GRAPHS, 32>>>(batch, out, n);
}

// round 10
// speedup vs baseline: 1.0591x; 1.0591x over previous
#include <cuda_runtime.h>

#define N_NODES  50000
#define N_EDGES  800000
#define N_GRAPHS 128
#define D        128

// Scratch (device globals — no allocation allowed)
__device__ float g_hw[N_NODES * D];     // (H @ W) * dinv[row]
__device__ float g_agg[N_NODES * D];    // layer-1 aggregated output
__device__ float4 g_z[N_NODES];         // folded layer-3 features (3 used)
__device__ float4 g_zagg[N_NODES];      // aggregated layer-3 output
__device__ float g_dinv[N_NODES];
__device__ int   g_ecnt[N_NODES];       // zero-init; re-zeroed by scan each replay
__device__ int   g_off[N_NODES + 1];    // CSR offsets
__device__ int   g_cur[N_NODES];        // fill cursors
__device__ int   g_srcs[N_EDGES];       // src node ids, grouped by dst
__device__ float4 g_wfold[D];           // W3 @ Wlin rows (xyz used)
__device__ float4 g_bfold;              // b3 @ Wlin + blin

// ---------------------------------------------------------------------------
// Fold W3@Wlin (+ b3@Wlin+blin): 129 blocks x 32 threads, shfl reduce.
// ---------------------------------------------------------------------------
__global__ __launch_bounds__(32) void fold_kernel(const float* __restrict__ W3,
                                                  const float* __restrict__ b3,
                                                  const float* __restrict__ Wlin,
                                                  const float* __restrict__ blin) {
    const int r    = blockIdx.x;     // 0..127 rows, 128 = bias
    const int lane = threadIdx.x;
    float a0 = 0.f, a1 = 0.f, a2 = 0.f;
    const float* vec = (r < D) ? (W3 + r * D) : b3;
#pragma unroll
    for (int k = lane; k < D; k += 32) {
        float w = vec[k];
        a0 = fmaf(w, Wlin[k * 3 + 0], a0);
        a1 = fmaf(w, Wlin[k * 3 + 1], a1);
        a2 = fmaf(w, Wlin[k * 3 + 2], a2);
    }
#pragma unroll
    for (int m = 16; m > 0; m >>= 1) {
        a0 += __shfl_xor_sync(0xffffffff, a0, m);
        a1 += __shfl_xor_sync(0xffffffff, a1, m);
        a2 += __shfl_xor_sync(0xffffffff, a2, m);
    }
    if (lane == 0) {
        if (r < D) g_wfold[r] = make_float4(a0, a1, a2, 0.f);
        else       g_bfold   = make_float4(a0 + blin[0], a1 + blin[1], a2 + blin[2], 0.f);
    }
}

// ---------------------------------------------------------------------------
// CSR build: histogram -> scan (+dinv, +self-reset) -> fill
// ---------------------------------------------------------------------------
__global__ void hist_kernel(const int* __restrict__ ei, int E) {
    int e = blockIdx.x * blockDim.x + threadIdx.x;
    if (e < E) atomicAdd(&g_ecnt[ei[E + e]], 1);
}

__global__ void scan_kernel(int n) {
    __shared__ int part[1024];
    const int t = threadIdx.x;
    const int chunk = (n + 1023) / 1024;
    const int s = t * chunk;
    const int e = min(s + chunk, n);
    int sum = 0;
    for (int i = s; i < e; i++) sum += g_ecnt[i];
    part[t] = sum;
    __syncthreads();
    for (int d = 1; d < 1024; d <<= 1) {
        int v = (t >= d) ? part[t - d] : 0;
        __syncthreads();
        part[t] += v;
        __syncthreads();
    }
    int run = part[t] - sum;
    for (int i = s; i < e; i++) {
        int c = g_ecnt[i];
        g_ecnt[i] = 0;                        // reset for next replay
        g_off[i] = run;
        g_cur[i] = run;
        g_dinv[i] = rsqrtf((float)(c + 1));   // +1 self-loop
        run += c;
    }
    if (e == n && s < n) g_off[n] = run;
}

__global__ void fill_kernel(const int* __restrict__ ei, int E) {
    int e = blockIdx.x * blockDim.x + threadIdx.x;
    if (e >= E) return;
    int row = ei[e];
    int col = ei[E + e];
    int pos = atomicAdd(&g_cur[col], 1);
    g_srcs[pos] = row;
}

// ---------------------------------------------------------------------------
// packed f32x2 helpers
// ---------------------------------------------------------------------------
__device__ __forceinline__ unsigned long long bcast2(float v) {
    unsigned long long r;
    asm("mov.b64 %0, {%1, %1};" : "=l"(r) : "r"(__float_as_uint(v)));
    return r;
}
__device__ __forceinline__ void fma2(unsigned long long& acc,
                                     unsigned long long a,
                                     unsigned long long b) {
    asm("fma.rn.f32x2 %0, %1, %2, %0;" : "+l"(acc) : "l"(a), "l"(b));
}
__device__ __forceinline__ void mul2(unsigned long long& d,
                                     unsigned long long s) {
    asm("mul.rn.f32x2 %0, %0, %1;" : "+l"(d) : "l"(s));
}

// ---------------------------------------------------------------------------
// GEMM: OUT[r,:] = (act(H)[r,:] @ W) * dinv[r]
// R6 geometry: 128 threads, 64 rows/block, 8x8 per thread, 48KB smem.
// ---------------------------------------------------------------------------
template <bool RELU>
__global__ __launch_bounds__(128, 4) void gemm_kernel(const float* __restrict__ H,
                                                      const float* __restrict__ W,
                                                      float* __restrict__ OUT, int n) {
    __shared__ float sW[32 * D];   // 16KB (one k-chunk)
    __shared__ float sH[64 * D];   // 32KB

    const int tid  = threadIdx.x;
    const int row0 = blockIdx.x * 64;

#pragma unroll
    for (int i = 0; i < 16; i++) {
        int idx = (i * 128 + tid) * 4;
        int r   = row0 + (idx >> 7);
        float4 v;
        if (r < n) {
            v = *(const float4*)(H + r * D + (idx & 127));
            if (RELU) {
                v.x = fmaxf(v.x, 0.f); v.y = fmaxf(v.y, 0.f);
                v.z = fmaxf(v.z, 0.f); v.w = fmaxf(v.w, 0.f);
            }
        } else {
            v = make_float4(0.f, 0.f, 0.f, 0.f);
        }
        *(float4*)(sH + idx) = v;
    }

    const int tx = tid & 15;
    const int ty = tid >> 4;

    unsigned long long acc[8][4] = {};

#pragma unroll
    for (int kc = 0; kc < 4; kc++) {
        __syncthreads();
#pragma unroll
        for (int i = 0; i < 8; i++) {
            int idx = (i * 128 + tid) * 4;
            *(float4*)(sW + idx) = *(const float4*)(W + kc * 32 * D + idx);
        }
        __syncthreads();

#pragma unroll 2
        for (int k = 0; k < 32; k += 4) {
            const int hk = kc * 32 + k;
            float4 h[8];
#pragma unroll
            for (int r = 0; r < 8; r++)
                h[r] = *(float4*)(sH + (ty * 8 + r) * D + hk);

#pragma unroll
            for (int kk = 0; kk < 4; kk++) {
                const ulonglong2* wr = (const ulonglong2*)(sW + (k + kk) * D + tx * 8);
                ulonglong2 wa = wr[0];
                ulonglong2 wb = wr[1];
#pragma unroll
                for (int r = 0; r < 8; r++) {
                    float hv = (kk == 0) ? h[r].x : (kk == 1) ? h[r].y
                             : (kk == 2) ? h[r].z : h[r].w;
                    unsigned long long p = bcast2(hv);
                    fma2(acc[r][0], p, wa.x);
                    fma2(acc[r][1], p, wa.y);
                    fma2(acc[r][2], p, wb.x);
                    fma2(acc[r][3], p, wb.y);
                }
            }
        }
    }

    const int col = tx * 8;
#pragma unroll
    for (int i = 0; i < 8; i++) {
        int r = row0 + ty * 8 + i;
        if (r < n) {
            unsigned long long sp = bcast2(g_dinv[r]);
            mul2(acc[i][0], sp); mul2(acc[i][1], sp);
            mul2(acc[i][2], sp); mul2(acc[i][3], sp);
            ulonglong2* o = (ulonglong2*)(OUT + r * D + col);
            o[0] = make_ulonglong2(acc[i][0], acc[i][1]);
            o[1] = make_ulonglong2(acc[i][2], acc[i][3]);
        }
    }
}

// ---------------------------------------------------------------------------
// Gather aggregation (warp per node, float4 per lane):
// row = dinv[i] * (hw'[i] + sum_in hw'[src]) + b
// FUSE_HEAD=false: write row to g_agg.
// FUSE_HEAD=true : relu(row) @ Wfold (smem) -> warp reduce -> g_z[i] *= dinv.
// ---------------------------------------------------------------------------
template <bool FUSE_HEAD>
__global__ __launch_bounds__(256) void gather_kernel(const float* __restrict__ b, int n) {
    __shared__ float4 swf[D];
    if (FUSE_HEAD) {
        if (threadIdx.x < D) swf[threadIdx.x] = g_wfold[threadIdx.x];
        __syncthreads();
    }

    const int node = blockIdx.x * 8 + (threadIdx.x >> 5);
    const int lane = threadIdx.x & 31;
    if (node >= n) return;

    const float4* __restrict__ hw4 = (const float4*)g_hw;
    float4 acc = hw4[node * 32 + lane];

    const int off = g_off[node];
    const int deg = g_off[node + 1] - off;
    const int* __restrict__ src = g_srcs + off;

    int j = 0;
    for (; j + 8 <= deg; j += 8) {
        int s0 = src[j + 0], s1 = src[j + 1], s2 = src[j + 2], s3 = src[j + 3];
        int s4 = src[j + 4], s5 = src[j + 5], s6 = src[j + 6], s7 = src[j + 7];
        float4 v0 = __ldg(hw4 + s0 * 32 + lane);
        float4 v1 = __ldg(hw4 + s1 * 32 + lane);
        float4 v2 = __ldg(hw4 + s2 * 32 + lane);
        float4 v3 = __ldg(hw4 + s3 * 32 + lane);
        float4 v4 = __ldg(hw4 + s4 * 32 + lane);
        float4 v5 = __ldg(hw4 + s5 * 32 + lane);
        float4 v6 = __ldg(hw4 + s6 * 32 + lane);
        float4 v7 = __ldg(hw4 + s7 * 32 + lane);
        acc.x += (v0.x + v1.x) + (v2.x + v3.x) + ((v4.x + v5.x) + (v6.x + v7.x));
        acc.y += (v0.y + v1.y) + (v2.y + v3.y) + ((v4.y + v5.y) + (v6.y + v7.y));
        acc.z += (v0.z + v1.z) + (v2.z + v3.z) + ((v4.z + v5.z) + (v6.z + v7.z));
        acc.w += (v0.w + v1.w) + (v2.w + v3.w) + ((v4.w + v5.w) + (v6.w + v7.w));
    }
    for (; j + 4 <= deg; j += 4) {
        int s0 = src[j + 0], s1 = src[j + 1], s2 = src[j + 2], s3 = src[j + 3];
        float4 v0 = __ldg(hw4 + s0 * 32 + lane);
        float4 v1 = __ldg(hw4 + s1 * 32 + lane);
        float4 v2 = __ldg(hw4 + s2 * 32 + lane);
        float4 v3 = __ldg(hw4 + s3 * 32 + lane);
        acc.x += (v0.x + v1.x) + (v2.x + v3.x);
        acc.y += (v0.y + v1.y) + (v2.y + v3.y);
        acc.z += (v0.z + v1.z) + (v2.z + v3.z);
        acc.w += (v0.w + v1.w) + (v2.w + v3.w);
    }
    for (; j < deg; j++) {
        float4 v = __ldg(hw4 + src[j] * 32 + lane);
        acc.x += v.x; acc.y += v.y; acc.z += v.z; acc.w += v.w;
    }

    float s = g_dinv[node];
    float4 bb = ((const float4*)b)[lane];
    float4 row;
    row.x = fmaf(acc.x, s, bb.x);
    row.y = fmaf(acc.y, s, bb.y);
    row.z = fmaf(acc.z, s, bb.z);
    row.w = fmaf(acc.w, s, bb.w);

    if (!FUSE_HEAD) {
        ((float4*)g_agg)[node * 32 + lane] = row;
    } else {
        // relu + [1x128]@[128x3] via smem Wfold + warp reduce
        row.x = fmaxf(row.x, 0.f); row.y = fmaxf(row.y, 0.f);
        row.z = fmaxf(row.z, 0.f); row.w = fmaxf(row.w, 0.f);
        float4 w0 = swf[lane * 4 + 0];
        float4 w1 = swf[lane * 4 + 1];
        float4 w2 = swf[lane * 4 + 2];
        float4 w3 = swf[lane * 4 + 3];
        float a0 = row.x * w0.x + row.y * w1.x + row.z * w2.x + row.w * w3.x;
        float a1 = row.x * w0.y + row.y * w1.y + row.z * w2.y + row.w * w3.y;
        float a2 = row.x * w0.z + row.y * w1.z + row.z * w2.z + row.w * w3.z;
#pragma unroll
        for (int m = 16; m > 0; m >>= 1) {
            a0 += __shfl_xor_sync(0xffffffff, a0, m);
            a1 += __shfl_xor_sync(0xffffffff, a1, m);
            a2 += __shfl_xor_sync(0xffffffff, a2, m);
        }
        if (lane == 0)
            g_z[node] = make_float4(a0 * s, a1 * s, a2 * s, 0.f);
    }
}

// ---------------------------------------------------------------------------
// gather3: zagg[i] = dinv[i] * (z[i] + sum_in z[src])
// ---------------------------------------------------------------------------
__global__ __launch_bounds__(256) void gather3_kernel(int n) {
    const int node = blockIdx.x * blockDim.x + threadIdx.x;
    if (node >= n) return;

    float4 zv = g_z[node];
    float a0 = zv.x, a1 = zv.y, a2 = zv.z;

    const int off = g_off[node];
    const int deg = g_off[node + 1] - off;
    const int* __restrict__ src = g_srcs + off;

    int j = 0;
    for (; j + 4 <= deg; j += 4) {
        float4 v0 = __ldg(&g_z[src[j + 0]]);
        float4 v1 = __ldg(&g_z[src[j + 1]]);
        float4 v2 = __ldg(&g_z[src[j + 2]]);
        float4 v3 = __ldg(&g_z[src[j + 3]]);
        a0 += (v0.x + v1.x) + (v2.x + v3.x);
        a1 += (v0.y + v1.y) + (v2.y + v3.y);
        a2 += (v0.z + v1.z) + (v2.z + v3.z);
    }
    for (; j < deg; j++) {
        float4 v = __ldg(&g_z[src[j]]);
        a0 += v.x; a1 += v.y; a2 += v.z;
    }
    float s = g_dinv[node];
    g_zagg[node] = make_float4(a0 * s, a1 * s, a2 * s, 0.f);
}

// ---------------------------------------------------------------------------
// pool: out[g] = mean over batch-range of zagg + bfold   (1 warp per graph)
// ---------------------------------------------------------------------------
__global__ __launch_bounds__(32) void pool_kernel(const int* __restrict__ batch,
                                                  float* __restrict__ out, int n) {
    const int g = blockIdx.x;
    const int lane = threadIdx.x;

    int target = g + (lane & 1);
    int lo = 0, hi = n;
    while (lo < hi) {
        int m = (lo + hi) >> 1;
        if (batch[m] < target) lo = m + 1; else hi = m;
    }
    int start = __shfl_sync(0xffffffff, lo, 0);
    int end   = __shfl_sync(0xffffffff, lo, 1);

    float a0 = 0.f, a1 = 0.f, a2 = 0.f;
    for (int i = start + lane; i < end; i += 32) {
        float4 v = g_zagg[i];
        a0 += v.x; a1 += v.y; a2 += v.z;
    }
#pragma unroll
    for (int m = 16; m > 0; m >>= 1) {
        a0 += __shfl_xor_sync(0xffffffff, a0, m);
        a1 += __shfl_xor_sync(0xffffffff, a1, m);
        a2 += __shfl_xor_sync(0xffffffff, a2, m);
    }
    if (lane == 0) {
        float inv = 1.f / fmaxf((float)(end - start), 1.f);
        float4 bf = g_bfold;
        out[g * 3 + 0] = fmaf(a0, inv, bf.x);
        out[g * 3 + 1] = fmaf(a1, inv, bf.y);
        out[g * 3 + 2] = fmaf(a2, inv, bf.z);
    }
}

// ---------------------------------------------------------------------------
// launch (sequential; profile slot 5 = gather1)
// ---------------------------------------------------------------------------
extern "C" void kernel_launch(void* const* d_in, const int* in_sizes, int n_in,
                              void* d_out, int out_size) {
    const float* x     = (const float*)d_in[0];
    const int*   ei    = (const int*)  d_in[1];
    const int*   batch = (const int*)  d_in[2];
    const float* W1    = (const float*)d_in[3];
    const float* b1    = (const float*)d_in[4];
    const float* W2    = (const float*)d_in[5];
    const float* b2    = (const float*)d_in[6];
    const float* W3    = (const float*)d_in[7];
    const float* b3    = (const float*)d_in[8];
    const float* Wlin  = (const float*)d_in[9];
    const float* blin  = (const float*)d_in[10];
    float* out = (float*)d_out;

    const int n = in_sizes[0] / D;   // 50000
    const int E = in_sizes[1] / 2;   // 800000

    float* hw_ptr;
    cudaGetSymbolAddress((void**)&hw_ptr, g_hw);
    float* agg_ptr;
    cudaGetSymbolAddress((void**)&agg_ptr, g_agg);

    const int gemm_blocks = (n + 63) / 64;
    const int gath_blocks = (n + 7) / 8;

    // CSR build + fold (launches 0-3)
    hist_kernel<<<(E + 255) / 256, 256>>>(ei, E);
    scan_kernel<<<1, 1024>>>(n);
    fill_kernel<<<(E + 255) / 256, 256>>>(ei, E);
    fold_kernel<<<D + 1, 32>>>(W3, b3, Wlin, blin);

    // layer 1 (launch 4 = gemm, launch 5 = gather1 -> profiled)
    gemm_kernel<false><<<gemm_blocks, 128>>>(x, W1, hw_ptr, n);
    gather_kernel<false><<<gath_blocks, 256>>>(b1, n);

    // layer 2 + fused folded head (relu in GEMM load; relu+head in gather)
    gemm_kernel<true><<<gemm_blocks, 128>>>(agg_ptr, W2, hw_ptr, n);
    gather_kernel<true><<<gath_blocks, 256>>>(b2, n);

    // layer 3 message passing on 3-wide features
    gather3_kernel<<<(n + 255) / 256, 256>>>(n);

    // mean pool + bias
    pool_kernel<<<N_GRAPHS, 32>>>(batch, out, n);
}

// round 11
// speedup vs baseline: 1.1227x; 1.0600x over previous
#include <cuda_runtime.h>

#define N_NODES  50000
#define N_EDGES  800000
#define N_GRAPHS 128
#define D        128

// Scratch (device globals — no allocation allowed)
__device__ float g_hw[N_NODES * D];     // (H @ W) * dinv[row]
__device__ float g_agg[N_NODES * D];    // layer-1 aggregated output
__device__ float4 g_z[N_NODES];         // folded layer-3 features (3 used)
__device__ float4 g_zagg[N_NODES];      // aggregated layer-3 output
__device__ float g_dinv[N_NODES];
__device__ int   g_ecnt[N_NODES];       // zero-init; re-zeroed by scan each replay
__device__ int   g_off[N_NODES + 1];    // CSR offsets
__device__ int   g_cur[N_NODES];        // fill cursors
__device__ int   g_srcs[N_EDGES];       // src node ids, grouped by dst
__device__ float4 g_wfold[D];           // W3 @ Wlin rows (xyz used)
__device__ float4 g_bfold;              // b3 @ Wlin + blin

// ---------------------------------------------------------------------------
// Streams/events for fork-join inside CUDA-graph capture (created once;
// no device memory involved).
// ---------------------------------------------------------------------------
static cudaStream_t g_side_stream;
static cudaEvent_t  g_ev_fork, g_ev_join;
static struct StreamInit {
    StreamInit() {
        cudaStreamCreateWithFlags(&g_side_stream, cudaStreamNonBlocking);
        cudaEventCreateWithFlags(&g_ev_fork, cudaEventDisableTiming);
        cudaEventCreateWithFlags(&g_ev_join, cudaEventDisableTiming);
    }
} g_stream_init;

// ---------------------------------------------------------------------------
// Fold W3@Wlin (+ b3@Wlin+blin): 129 blocks x 32 threads, shfl reduce.
// ---------------------------------------------------------------------------
__global__ __launch_bounds__(32) void fold_kernel(const float* __restrict__ W3,
                                                  const float* __restrict__ b3,
                                                  const float* __restrict__ Wlin,
                                                  const float* __restrict__ blin) {
    const int r    = blockIdx.x;     // 0..127 rows, 128 = bias
    const int lane = threadIdx.x;
    float a0 = 0.f, a1 = 0.f, a2 = 0.f;
    const float* vec = (r < D) ? (W3 + r * D) : b3;
#pragma unroll
    for (int k = lane; k < D; k += 32) {
        float w = vec[k];
        a0 = fmaf(w, Wlin[k * 3 + 0], a0);
        a1 = fmaf(w, Wlin[k * 3 + 1], a1);
        a2 = fmaf(w, Wlin[k * 3 + 2], a2);
    }
#pragma unroll
    for (int m = 16; m > 0; m >>= 1) {
        a0 += __shfl_xor_sync(0xffffffff, a0, m);
        a1 += __shfl_xor_sync(0xffffffff, a1, m);
        a2 += __shfl_xor_sync(0xffffffff, a2, m);
    }
    if (lane == 0) {
        if (r < D) g_wfold[r] = make_float4(a0, a1, a2, 0.f);
        else       g_bfold   = make_float4(a0 + blin[0], a1 + blin[1], a2 + blin[2], 0.f);
    }
}

// ---------------------------------------------------------------------------
// CSR build: histogram (int4) -> scan (+dinv, +self-reset) -> fill (int4)
// ---------------------------------------------------------------------------
__global__ void hist_kernel(const int* __restrict__ ei, int E) {
    int e = (blockIdx.x * blockDim.x + threadIdx.x) * 4;
    if (e + 3 < E) {
        int4 c = *(const int4*)(ei + E + e);
        atomicAdd(&g_ecnt[c.x], 1);
        atomicAdd(&g_ecnt[c.y], 1);
        atomicAdd(&g_ecnt[c.z], 1);
        atomicAdd(&g_ecnt[c.w], 1);
    } else {
        for (; e < E; e++) atomicAdd(&g_ecnt[ei[E + e]], 1);
    }
}

__global__ void scan_kernel(int n) {
    __shared__ int part[1024];
    const int t = threadIdx.x;
    const int chunk = (n + 1023) / 1024;
    const int s = t * chunk;
    const int e = min(s + chunk, n);
    int sum = 0;
    for (int i = s; i < e; i++) sum += g_ecnt[i];
    part[t] = sum;
    __syncthreads();
    for (int d = 1; d < 1024; d <<= 1) {
        int v = (t >= d) ? part[t - d] : 0;
        __syncthreads();
        part[t] += v;
        __syncthreads();
    }
    int run = part[t] - sum;
    for (int i = s; i < e; i++) {
        int c = g_ecnt[i];
        g_ecnt[i] = 0;                        // reset for next replay
        g_off[i] = run;
        g_cur[i] = run;
        g_dinv[i] = rsqrtf((float)(c + 1));   // +1 self-loop
        run += c;
    }
    if (e == n && s < n) g_off[n] = run;
}

__global__ void fill_kernel(const int* __restrict__ ei, int E) {
    int e = (blockIdx.x * blockDim.x + threadIdx.x) * 4;
    if (e + 3 < E) {
        int4 r = *(const int4*)(ei + e);
        int4 c = *(const int4*)(ei + E + e);
        g_srcs[atomicAdd(&g_cur[c.x], 1)] = r.x;
        g_srcs[atomicAdd(&g_cur[c.y], 1)] = r.y;
        g_srcs[atomicAdd(&g_cur[c.z], 1)] = r.z;
        g_srcs[atomicAdd(&g_cur[c.w], 1)] = r.w;
    } else {
        for (; e < E; e++)
            g_srcs[atomicAdd(&g_cur[ei[E + e]], 1)] = ei[e];
    }
}

// ---------------------------------------------------------------------------
// packed f32x2 helpers
// ---------------------------------------------------------------------------
__device__ __forceinline__ unsigned long long bcast2(float v) {
    unsigned long long r;
    asm("mov.b64 %0, {%1, %1};" : "=l"(r) : "r"(__float_as_uint(v)));
    return r;
}
__device__ __forceinline__ void fma2(unsigned long long& acc,
                                     unsigned long long a,
                                     unsigned long long b) {
    asm("fma.rn.f32x2 %0, %1, %2, %0;" : "+l"(acc) : "l"(a), "l"(b));
}
__device__ __forceinline__ void mul2(unsigned long long& d,
                                     unsigned long long s) {
    asm("mul.rn.f32x2 %0, %0, %1;" : "+l"(d) : "l"(s));
}

// ---------------------------------------------------------------------------
// GEMM: OUT[r,:] = (act(H)[r,:] @ W) * dinv[r]
// R6 geometry: 128 threads, 64 rows/block, 8x8 per thread, 48KB smem.
// ---------------------------------------------------------------------------
template <bool RELU>
__global__ __launch_bounds__(128, 4) void gemm_kernel(const float* __restrict__ H,
                                                      const float* __restrict__ W,
                                                      float* __restrict__ OUT, int n) {
    __shared__ float sW[32 * D];   // 16KB (one k-chunk)
    __shared__ float sH[64 * D];   // 32KB

    const int tid  = threadIdx.x;
    const int row0 = blockIdx.x * 64;

#pragma unroll
    for (int i = 0; i < 16; i++) {
        int idx = (i * 128 + tid) * 4;
        int r   = row0 + (idx >> 7);
        float4 v;
        if (r < n) {
            v = *(const float4*)(H + r * D + (idx & 127));
            if (RELU) {
                v.x = fmaxf(v.x, 0.f); v.y = fmaxf(v.y, 0.f);
                v.z = fmaxf(v.z, 0.f); v.w = fmaxf(v.w, 0.f);
            }
        } else {
            v = make_float4(0.f, 0.f, 0.f, 0.f);
        }
        *(float4*)(sH + idx) = v;
    }

    const int tx = tid & 15;
    const int ty = tid >> 4;

    unsigned long long acc[8][4] = {};

#pragma unroll
    for (int kc = 0; kc < 4; kc++) {
        __syncthreads();
#pragma unroll
        for (int i = 0; i < 8; i++) {
            int idx = (i * 128 + tid) * 4;
            *(float4*)(sW + idx) = *(const float4*)(W + kc * 32 * D + idx);
        }
        __syncthreads();

#pragma unroll 2
        for (int k = 0; k < 32; k += 4) {
            const int hk = kc * 32 + k;
            float4 h[8];
#pragma unroll
            for (int r = 0; r < 8; r++)
                h[r] = *(float4*)(sH + (ty * 8 + r) * D + hk);

#pragma unroll
            for (int kk = 0; kk < 4; kk++) {
                const ulonglong2* wr = (const ulonglong2*)(sW + (k + kk) * D + tx * 8);
                ulonglong2 wa = wr[0];
                ulonglong2 wb = wr[1];
#pragma unroll
                for (int r = 0; r < 8; r++) {
                    float hv = (kk == 0) ? h[r].x : (kk == 1) ? h[r].y
                             : (kk == 2) ? h[r].z : h[r].w;
                    unsigned long long p = bcast2(hv);
                    fma2(acc[r][0], p, wa.x);
                    fma2(acc[r][1], p, wa.y);
                    fma2(acc[r][2], p, wb.x);
                    fma2(acc[r][3], p, wb.y);
                }
            }
        }
    }

    const int col = tx * 8;
#pragma unroll
    for (int i = 0; i < 8; i++) {
        int r = row0 + ty * 8 + i;
        if (r < n) {
            unsigned long long sp = bcast2(g_dinv[r]);
            mul2(acc[i][0], sp); mul2(acc[i][1], sp);
            mul2(acc[i][2], sp); mul2(acc[i][3], sp);
            ulonglong2* o = (ulonglong2*)(OUT + r * D + col);
            o[0] = make_ulonglong2(acc[i][0], acc[i][1]);
            o[1] = make_ulonglong2(acc[i][2], acc[i][3]);
        }
    }
}

// ---------------------------------------------------------------------------
// Gather aggregation (warp per node, float4 per lane):
// row = dinv[i] * (hw'[i] + sum_in hw'[src]) + b
// FUSE_HEAD=false: write row to g_agg.
// FUSE_HEAD=true : relu(row) @ Wfold (smem) -> warp reduce -> g_z[i] *= dinv.
// ---------------------------------------------------------------------------
template <bool FUSE_HEAD>
__global__ __launch_bounds__(256) void gather_kernel(const float* __restrict__ b, int n) {
    __shared__ float4 swf[D];
    if (FUSE_HEAD) {
        if (threadIdx.x < D) swf[threadIdx.x] = g_wfold[threadIdx.x];
        __syncthreads();
    }

    const int node = blockIdx.x * 8 + (threadIdx.x >> 5);
    const int lane = threadIdx.x & 31;
    if (node >= n) return;

    const float4* __restrict__ hw4 = (const float4*)g_hw;
    float4 acc = hw4[node * 32 + lane];

    const int off = g_off[node];
    const int deg = g_off[node + 1] - off;
    const int* __restrict__ src = g_srcs + off;

    int j = 0;
    for (; j + 8 <= deg; j += 8) {
        int s0 = src[j + 0], s1 = src[j + 1], s2 = src[j + 2], s3 = src[j + 3];
        int s4 = src[j + 4], s5 = src[j + 5], s6 = src[j + 6], s7 = src[j + 7];
        float4 v0 = __ldg(hw4 + s0 * 32 + lane);
        float4 v1 = __ldg(hw4 + s1 * 32 + lane);
        float4 v2 = __ldg(hw4 + s2 * 32 + lane);
        float4 v3 = __ldg(hw4 + s3 * 32 + lane);
        float4 v4 = __ldg(hw4 + s4 * 32 + lane);
        float4 v5 = __ldg(hw4 + s5 * 32 + lane);
        float4 v6 = __ldg(hw4 + s6 * 32 + lane);
        float4 v7 = __ldg(hw4 + s7 * 32 + lane);
        acc.x += (v0.x + v1.x) + (v2.x + v3.x) + ((v4.x + v5.x) + (v6.x + v7.x));
        acc.y += (v0.y + v1.y) + (v2.y + v3.y) + ((v4.y + v5.y) + (v6.y + v7.y));
        acc.z += (v0.z + v1.z) + (v2.z + v3.z) + ((v4.z + v5.z) + (v6.z + v7.z));
        acc.w += (v0.w + v1.w) + (v2.w + v3.w) + ((v4.w + v5.w) + (v6.w + v7.w));
    }
    for (; j + 4 <= deg; j += 4) {
        int s0 = src[j + 0], s1 = src[j + 1], s2 = src[j + 2], s3 = src[j + 3];
        float4 v0 = __ldg(hw4 + s0 * 32 + lane);
        float4 v1 = __ldg(hw4 + s1 * 32 + lane);
        float4 v2 = __ldg(hw4 + s2 * 32 + lane);
        float4 v3 = __ldg(hw4 + s3 * 32 + lane);
        acc.x += (v0.x + v1.x) + (v2.x + v3.x);
        acc.y += (v0.y + v1.y) + (v2.y + v3.y);
        acc.z += (v0.z + v1.z) + (v2.z + v3.z);
        acc.w += (v0.w + v1.w) + (v2.w + v3.w);
    }
    for (; j < deg; j++) {
        float4 v = __ldg(hw4 + src[j] * 32 + lane);
        acc.x += v.x; acc.y += v.y; acc.z += v.z; acc.w += v.w;
    }

    float s = g_dinv[node];
    float4 bb = ((const float4*)b)[lane];
    float4 row;
    row.x = fmaf(acc.x, s, bb.x);
    row.y = fmaf(acc.y, s, bb.y);
    row.z = fmaf(acc.z, s, bb.z);
    row.w = fmaf(acc.w, s, bb.w);

    if (!FUSE_HEAD) {
        ((float4*)g_agg)[node * 32 + lane] = row;
    } else {
        row.x = fmaxf(row.x, 0.f); row.y = fmaxf(row.y, 0.f);
        row.z = fmaxf(row.z, 0.f); row.w = fmaxf(row.w, 0.f);
        float4 w0 = swf[lane * 4 + 0];
        float4 w1 = swf[lane * 4 + 1];
        float4 w2 = swf[lane * 4 + 2];
        float4 w3 = swf[lane * 4 + 3];
        float a0 = row.x * w0.x + row.y * w1.x + row.z * w2.x + row.w * w3.x;
        float a1 = row.x * w0.y + row.y * w1.y + row.z * w2.y + row.w * w3.y;
        float a2 = row.x * w0.z + row.y * w1.z + row.z * w2.z + row.w * w3.z;
#pragma unroll
        for (int m = 16; m > 0; m >>= 1) {
            a0 += __shfl_xor_sync(0xffffffff, a0, m);
            a1 += __shfl_xor_sync(0xffffffff, a1, m);
            a2 += __shfl_xor_sync(0xffffffff, a2, m);
        }
        if (lane == 0)
            g_z[node] = make_float4(a0 * s, a1 * s, a2 * s, 0.f);
    }
}

// ---------------------------------------------------------------------------
// gather3: zagg[i] = dinv[i] * (z[i] + sum_in z[src])
// ---------------------------------------------------------------------------
__global__ __launch_bounds__(256) void gather3_kernel(int n) {
    const int node = blockIdx.x * blockDim.x + threadIdx.x;
    if (node >= n) return;

    float4 zv = g_z[node];
    float a0 = zv.x, a1 = zv.y, a2 = zv.z;

    const int off = g_off[node];
    const int deg = g_off[node + 1] - off;
    const int* __restrict__ src = g_srcs + off;

    int j = 0;
    for (; j + 4 <= deg; j += 4) {
        float4 v0 = __ldg(&g_z[src[j + 0]]);
        float4 v1 = __ldg(&g_z[src[j + 1]]);
        float4 v2 = __ldg(&g_z[src[j + 2]]);
        float4 v3 = __ldg(&g_z[src[j + 3]]);
        a0 += (v0.x + v1.x) + (v2.x + v3.x);
        a1 += (v0.y + v1.y) + (v2.y + v3.y);
        a2 += (v0.z + v1.z) + (v2.z + v3.z);
    }
    for (; j < deg; j++) {
        float4 v = __ldg(&g_z[src[j]]);
        a0 += v.x; a1 += v.y; a2 += v.z;
    }
    float s = g_dinv[node];
    g_zagg[node] = make_float4(a0 * s, a1 * s, a2 * s, 0.f);
}

// ---------------------------------------------------------------------------
// pool: out[g] = mean over batch-range of zagg + bfold   (1 warp per graph)
// ---------------------------------------------------------------------------
__global__ __launch_bounds__(32) void pool_kernel(const int* __restrict__ batch,
                                                  float* __restrict__ out, int n) {
    const int g = blockIdx.x;
    const int lane = threadIdx.x;

    int target = g + (lane & 1);
    int lo = 0, hi = n;
    while (lo < hi) {
        int m = (lo + hi) >> 1;
        if (batch[m] < target) lo = m + 1; else hi = m;
    }
    int start = __shfl_sync(0xffffffff, lo, 0);
    int end   = __shfl_sync(0xffffffff, lo, 1);

    float a0 = 0.f, a1 = 0.f, a2 = 0.f;
    for (int i = start + lane; i < end; i += 32) {
        float4 v = g_zagg[i];
        a0 += v.x; a1 += v.y; a2 += v.z;
    }
#pragma unroll
    for (int m = 16; m > 0; m >>= 1) {
        a0 += __shfl_xor_sync(0xffffffff, a0, m);
        a1 += __shfl_xor_sync(0xffffffff, a1, m);
        a2 += __shfl_xor_sync(0xffffffff, a2, m);
    }
    if (lane == 0) {
        float inv = 1.f / fmaxf((float)(end - start), 1.f);
        float4 bf = g_bfold;
        out[g * 3 + 0] = fmaf(a0, inv, bf.x);
        out[g * 3 + 1] = fmaf(a1, inv, bf.y);
        out[g * 3 + 2] = fmaf(a2, inv, bf.z);
    }
}

// ---------------------------------------------------------------------------
// launch: hist -> scan, then fork {fill, fold} || gemm1, join, rest sequential
// ---------------------------------------------------------------------------
extern "C" void kernel_launch(void* const* d_in, const int* in_sizes, int n_in,
                              void* d_out, int out_size) {
    const float* x     = (const float*)d_in[0];
    const int*   ei    = (const int*)  d_in[1];
    const int*   batch = (const int*)  d_in[2];
    const float* W1    = (const float*)d_in[3];
    const float* b1    = (const float*)d_in[4];
    const float* W2    = (const float*)d_in[5];
    const float* b2    = (const float*)d_in[6];
    const float* W3    = (const float*)d_in[7];
    const float* b3    = (const float*)d_in[8];
    const float* Wlin  = (const float*)d_in[9];
    const float* blin  = (const float*)d_in[10];
    float* out = (float*)d_out;

    const int n = in_sizes[0] / D;   // 50000
    const int E = in_sizes[1] / 2;   // 800000

    float* hw_ptr;
    cudaGetSymbolAddress((void**)&hw_ptr, g_hw);
    float* agg_ptr;
    cudaGetSymbolAddress((void**)&agg_ptr, g_agg);

    const int gemm_blocks = (n + 63) / 64;
    const int gath_blocks = (n + 7) / 8;
    const int e4_blocks   = ((E + 3) / 4 + 255) / 256;

    // sequential prefix: hist -> scan (dinv ready for gemm1 epilogue)
    hist_kernel<<<e4_blocks, 256>>>(ei, E);
    scan_kernel<<<1, 1024>>>(n);

    // fork: side stream does fill + fold while main stream runs GEMM1
    cudaEventRecord(g_ev_fork, 0);
    cudaStreamWaitEvent(g_side_stream, g_ev_fork, 0);
    fill_kernel<<<e4_blocks, 256, 0, g_side_stream>>>(ei, E);
    fold_kernel<<<D + 1, 32, 0, g_side_stream>>>(W3, b3, Wlin, blin);
    cudaEventRecord(g_ev_join, g_side_stream);

    gemm_kernel<false><<<gemm_blocks, 128>>>(x, W1, hw_ptr, n);

    cudaStreamWaitEvent(0, g_ev_join, 0);

    // layer 1 aggregation
    gather_kernel<false><<<gath_blocks, 256>>>(b1, n);

    // layer 2 + fused folded head
    gemm_kernel<true><<<gemm_blocks, 128>>>(agg_ptr, W2, hw_ptr, n);
    gather_kernel<true><<<gath_blocks, 256>>>(b2, n);

    // layer 3 message passing on 3-wide features
    gather3_kernel<<<(n + 255) / 256, 256>>>(n);

    // mean pool + bias
    pool_kernel<<<N_GRAPHS, 32>>>(batch, out, n);
}

// round 12
// speedup vs baseline: 1.1838x; 1.0545x over previous
#include <cuda_runtime.h>
#include <cuda_bf16.h>

#define N_NODES  50000
#define N_EDGES  800000
#define N_GRAPHS 128
#define D        128

// Scratch (device globals — no allocation allowed)
__device__ __nv_bfloat16 g_hwb[N_NODES * D];  // (H @ W) * dinv[row], bf16
__device__ float g_agg[N_NODES * D];    // layer-1 aggregated output (fp32)
__device__ float4 g_z[N_NODES];         // folded layer-3 features (3 used)
__device__ float4 g_zagg[N_NODES];      // aggregated layer-3 output
__device__ float g_dinv[N_NODES];
__device__ int   g_ecnt[N_NODES];       // zero-init; re-zeroed by scan each replay
__device__ int   g_off[N_NODES + 1];    // CSR offsets
__device__ int   g_cur[N_NODES];        // fill cursors
__device__ int   g_srcs[N_EDGES];       // src node ids, grouped by dst
__device__ float4 g_wfold[D];           // W3 @ Wlin rows (xyz used)
__device__ float4 g_bfold;              // b3 @ Wlin + blin

// ---------------------------------------------------------------------------
// Streams/events for fork-join inside CUDA-graph capture (created once).
// ---------------------------------------------------------------------------
static cudaStream_t g_side_stream;
static cudaEvent_t  g_ev_fork, g_ev_join;
static struct StreamInit {
    StreamInit() {
        cudaStreamCreateWithFlags(&g_side_stream, cudaStreamNonBlocking);
        cudaEventCreateWithFlags(&g_ev_fork, cudaEventDisableTiming);
        cudaEventCreateWithFlags(&g_ev_join, cudaEventDisableTiming);
    }
} g_stream_init;

// ---------------------------------------------------------------------------
// bf16 pack/unpack helpers
// ---------------------------------------------------------------------------
__device__ __forceinline__ unsigned pack_bf16(float lo, float hi) {
    unsigned r;
    asm("cvt.rn.bf16x2.f32 %0, %1, %2;" : "=r"(r) : "f"(hi), "f"(lo));
    return r;
}
__device__ __forceinline__ float4 bf16x4_to_float4(uint2 w) {
    __nv_bfloat162 a = *reinterpret_cast<__nv_bfloat162*>(&w.x);
    __nv_bfloat162 b = *reinterpret_cast<__nv_bfloat162*>(&w.y);
    float2 fa = __bfloat1622float2(a);
    float2 fb = __bfloat1622float2(b);
    return make_float4(fa.x, fa.y, fb.x, fb.y);
}

// ---------------------------------------------------------------------------
// Fold W3@Wlin (+ b3@Wlin+blin): 129 blocks x 32 threads, shfl reduce.
// ---------------------------------------------------------------------------
__global__ __launch_bounds__(32) void fold_kernel(const float* __restrict__ W3,
                                                  const float* __restrict__ b3,
                                                  const float* __restrict__ Wlin,
                                                  const float* __restrict__ blin) {
    const int r    = blockIdx.x;     // 0..127 rows, 128 = bias
    const int lane = threadIdx.x;
    float a0 = 0.f, a1 = 0.f, a2 = 0.f;
    const float* vec = (r < D) ? (W3 + r * D) : b3;
#pragma unroll
    for (int k = lane; k < D; k += 32) {
        float w = vec[k];
        a0 = fmaf(w, Wlin[k * 3 + 0], a0);
        a1 = fmaf(w, Wlin[k * 3 + 1], a1);
        a2 = fmaf(w, Wlin[k * 3 + 2], a2);
    }
#pragma unroll
    for (int m = 16; m > 0; m >>= 1) {
        a0 += __shfl_xor_sync(0xffffffff, a0, m);
        a1 += __shfl_xor_sync(0xffffffff, a1, m);
        a2 += __shfl_xor_sync(0xffffffff, a2, m);
    }
    if (lane == 0) {
        if (r < D) g_wfold[r] = make_float4(a0, a1, a2, 0.f);
        else       g_bfold   = make_float4(a0 + blin[0], a1 + blin[1], a2 + blin[2], 0.f);
    }
}

// ---------------------------------------------------------------------------
// CSR build: histogram (int4) -> scan (+dinv, +self-reset) -> fill (int4)
// ---------------------------------------------------------------------------
__global__ void hist_kernel(const int* __restrict__ ei, int E) {
    int e = (blockIdx.x * blockDim.x + threadIdx.x) * 4;
    if (e + 3 < E) {
        int4 c = *(const int4*)(ei + E + e);
        atomicAdd(&g_ecnt[c.x], 1);
        atomicAdd(&g_ecnt[c.y], 1);
        atomicAdd(&g_ecnt[c.z], 1);
        atomicAdd(&g_ecnt[c.w], 1);
    } else {
        for (; e < E; e++) atomicAdd(&g_ecnt[ei[E + e]], 1);
    }
}

__global__ void scan_kernel(int n) {
    __shared__ int part[1024];
    const int t = threadIdx.x;
    const int chunk = (n + 1023) / 1024;
    const int s = t * chunk;
    const int e = min(s + chunk, n);
    int sum = 0;
    for (int i = s; i < e; i++) sum += g_ecnt[i];
    part[t] = sum;
    __syncthreads();
    for (int d = 1; d < 1024; d <<= 1) {
        int v = (t >= d) ? part[t - d] : 0;
        __syncthreads();
        part[t] += v;
        __syncthreads();
    }
    int run = part[t] - sum;
    for (int i = s; i < e; i++) {
        int c = g_ecnt[i];
        g_ecnt[i] = 0;                        // reset for next replay
        g_off[i] = run;
        g_cur[i] = run;
        g_dinv[i] = rsqrtf((float)(c + 1));   // +1 self-loop
        run += c;
    }
    if (e == n && s < n) g_off[n] = run;
}

__global__ void fill_kernel(const int* __restrict__ ei, int E) {
    int e = (blockIdx.x * blockDim.x + threadIdx.x) * 4;
    if (e + 3 < E) {
        int4 r = *(const int4*)(ei + e);
        int4 c = *(const int4*)(ei + E + e);
        g_srcs[atomicAdd(&g_cur[c.x], 1)] = r.x;
        g_srcs[atomicAdd(&g_cur[c.y], 1)] = r.y;
        g_srcs[atomicAdd(&g_cur[c.z], 1)] = r.z;
        g_srcs[atomicAdd(&g_cur[c.w], 1)] = r.w;
    } else {
        for (; e < E; e++)
            g_srcs[atomicAdd(&g_cur[ei[E + e]], 1)] = ei[e];
    }
}

// ---------------------------------------------------------------------------
// packed f32x2 helpers
// ---------------------------------------------------------------------------
__device__ __forceinline__ unsigned long long bcast2(float v) {
    unsigned long long r;
    asm("mov.b64 %0, {%1, %1};" : "=l"(r) : "r"(__float_as_uint(v)));
    return r;
}
__device__ __forceinline__ void fma2(unsigned long long& acc,
                                     unsigned long long a,
                                     unsigned long long b) {
    asm("fma.rn.f32x2 %0, %1, %2, %0;" : "+l"(acc) : "l"(a), "l"(b));
}
__device__ __forceinline__ void mul2(unsigned long long& d,
                                     unsigned long long s) {
    asm("mul.rn.f32x2 %0, %0, %1;" : "+l"(d) : "l"(s));
}
__device__ __forceinline__ float2 unpack2(unsigned long long v) {
    float2 f;
    asm("mov.b64 {%0, %1}, %2;" : "=f"(f.x), "=f"(f.y) : "l"(v));
    return f;
}

// ---------------------------------------------------------------------------
// GEMM: OUTB[r,:] = bf16( (act(H)[r,:] @ W) * dinv[r] )
// R6 geometry: 128 threads, 64 rows/block, 8x8 per thread, 48KB smem.
// ---------------------------------------------------------------------------
template <bool RELU>
__global__ __launch_bounds__(128, 4) void gemm_kernel(const float* __restrict__ H,
                                                      const float* __restrict__ W,
                                                      __nv_bfloat16* __restrict__ OUTB,
                                                      int n) {
    __shared__ float sW[32 * D];   // 16KB (one k-chunk)
    __shared__ float sH[64 * D];   // 32KB

    const int tid  = threadIdx.x;
    const int row0 = blockIdx.x * 64;

#pragma unroll
    for (int i = 0; i < 16; i++) {
        int idx = (i * 128 + tid) * 4;
        int r   = row0 + (idx >> 7);
        float4 v;
        if (r < n) {
            v = *(const float4*)(H + r * D + (idx & 127));
            if (RELU) {
                v.x = fmaxf(v.x, 0.f); v.y = fmaxf(v.y, 0.f);
                v.z = fmaxf(v.z, 0.f); v.w = fmaxf(v.w, 0.f);
            }
        } else {
            v = make_float4(0.f, 0.f, 0.f, 0.f);
        }
        *(float4*)(sH + idx) = v;
    }

    const int tx = tid & 15;
    const int ty = tid >> 4;

    unsigned long long acc[8][4] = {};

#pragma unroll
    for (int kc = 0; kc < 4; kc++) {
        __syncthreads();
#pragma unroll
        for (int i = 0; i < 8; i++) {
            int idx = (i * 128 + tid) * 4;
            *(float4*)(sW + idx) = *(const float4*)(W + kc * 32 * D + idx);
        }
        __syncthreads();

#pragma unroll 2
        for (int k = 0; k < 32; k += 4) {
            const int hk = kc * 32 + k;
            float4 h[8];
#pragma unroll
            for (int r = 0; r < 8; r++)
                h[r] = *(float4*)(sH + (ty * 8 + r) * D + hk);

#pragma unroll
            for (int kk = 0; kk < 4; kk++) {
                const ulonglong2* wr = (const ulonglong2*)(sW + (k + kk) * D + tx * 8);
                ulonglong2 wa = wr[0];
                ulonglong2 wb = wr[1];
#pragma unroll
                for (int r = 0; r < 8; r++) {
                    float hv = (kk == 0) ? h[r].x : (kk == 1) ? h[r].y
                             : (kk == 2) ? h[r].z : h[r].w;
                    unsigned long long p = bcast2(hv);
                    fma2(acc[r][0], p, wa.x);
                    fma2(acc[r][1], p, wa.y);
                    fma2(acc[r][2], p, wb.x);
                    fma2(acc[r][3], p, wb.y);
                }
            }
        }
    }

    // epilogue: *dinv, convert to bf16, STG.128 (16 uint4 per row)
#pragma unroll
    for (int i = 0; i < 8; i++) {
        int r = row0 + ty * 8 + i;
        if (r < n) {
            unsigned long long sp = bcast2(g_dinv[r]);
            mul2(acc[i][0], sp); mul2(acc[i][1], sp);
            mul2(acc[i][2], sp); mul2(acc[i][3], sp);
            float2 f0 = unpack2(acc[i][0]);
            float2 f1 = unpack2(acc[i][1]);
            float2 f2 = unpack2(acc[i][2]);
            float2 f3 = unpack2(acc[i][3]);
            uint4 o;
            o.x = pack_bf16(f0.x, f0.y);
            o.y = pack_bf16(f1.x, f1.y);
            o.z = pack_bf16(f2.x, f2.y);
            o.w = pack_bf16(f3.x, f3.y);
            ((uint4*)OUTB)[r * 16 + tx] = o;
        }
    }
}

// ---------------------------------------------------------------------------
// Gather aggregation (warp per node, 4 bf16 per lane via LDG.64):
// row = dinv[i] * (hw'[i] + sum_in hw'[src]) + b    (accumulate fp32)
// FUSE_HEAD=false: write row to g_agg (fp32).
// FUSE_HEAD=true : relu(row) @ Wfold (smem) -> warp reduce -> g_z[i] *= dinv.
// ---------------------------------------------------------------------------
template <bool FUSE_HEAD>
__global__ __launch_bounds__(256) void gather_kernel(const float* __restrict__ b, int n) {
    __shared__ float4 swf[D];
    if (FUSE_HEAD) {
        if (threadIdx.x < D) swf[threadIdx.x] = g_wfold[threadIdx.x];
        __syncthreads();
    }

    const int node = blockIdx.x * 8 + (threadIdx.x >> 5);
    const int lane = threadIdx.x & 31;
    if (node >= n) return;

    const uint2* __restrict__ hwb = (const uint2*)g_hwb;   // 32 uint2 per row
    float4 acc = bf16x4_to_float4(hwb[node * 32 + lane]);  // self term

    const int off = g_off[node];
    const int deg = g_off[node + 1] - off;
    const int* __restrict__ src = g_srcs + off;

    int j = 0;
    for (; j + 8 <= deg; j += 8) {
        uint2 w0 = __ldg(hwb + src[j + 0] * 32 + lane);
        uint2 w1 = __ldg(hwb + src[j + 1] * 32 + lane);
        uint2 w2 = __ldg(hwb + src[j + 2] * 32 + lane);
        uint2 w3 = __ldg(hwb + src[j + 3] * 32 + lane);
        uint2 w4 = __ldg(hwb + src[j + 4] * 32 + lane);
        uint2 w5 = __ldg(hwb + src[j + 5] * 32 + lane);
        uint2 w6 = __ldg(hwb + src[j + 6] * 32 + lane);
        uint2 w7 = __ldg(hwb + src[j + 7] * 32 + lane);
        float4 v0 = bf16x4_to_float4(w0);
        float4 v1 = bf16x4_to_float4(w1);
        float4 v2 = bf16x4_to_float4(w2);
        float4 v3 = bf16x4_to_float4(w3);
        float4 v4 = bf16x4_to_float4(w4);
        float4 v5 = bf16x4_to_float4(w5);
        float4 v6 = bf16x4_to_float4(w6);
        float4 v7 = bf16x4_to_float4(w7);
        acc.x += (v0.x + v1.x) + (v2.x + v3.x) + ((v4.x + v5.x) + (v6.x + v7.x));
        acc.y += (v0.y + v1.y) + (v2.y + v3.y) + ((v4.y + v5.y) + (v6.y + v7.y));
        acc.z += (v0.z + v1.z) + (v2.z + v3.z) + ((v4.z + v5.z) + (v6.z + v7.z));
        acc.w += (v0.w + v1.w) + (v2.w + v3.w) + ((v4.w + v5.w) + (v6.w + v7.w));
    }
    for (; j + 4 <= deg; j += 4) {
        uint2 w0 = __ldg(hwb + src[j + 0] * 32 + lane);
        uint2 w1 = __ldg(hwb + src[j + 1] * 32 + lane);
        uint2 w2 = __ldg(hwb + src[j + 2] * 32 + lane);
        uint2 w3 = __ldg(hwb + src[j + 3] * 32 + lane);
        float4 v0 = bf16x4_to_float4(w0);
        float4 v1 = bf16x4_to_float4(w1);
        float4 v2 = bf16x4_to_float4(w2);
        float4 v3 = bf16x4_to_float4(w3);
        acc.x += (v0.x + v1.x) + (v2.x + v3.x);
        acc.y += (v0.y + v1.y) + (v2.y + v3.y);
        acc.z += (v0.z + v1.z) + (v2.z + v3.z);
        acc.w += (v0.w + v1.w) + (v2.w + v3.w);
    }
    for (; j < deg; j++) {
        float4 v = bf16x4_to_float4(__ldg(hwb + src[j] * 32 + lane));
        acc.x += v.x; acc.y += v.y; acc.z += v.z; acc.w += v.w;
    }

    float s = g_dinv[node];
    float4 bb = ((const float4*)b)[lane];
    float4 row;
    row.x = fmaf(acc.x, s, bb.x);
    row.y = fmaf(acc.y, s, bb.y);
    row.z = fmaf(acc.z, s, bb.z);
    row.w = fmaf(acc.w, s, bb.w);

    if (!FUSE_HEAD) {
        ((float4*)g_agg)[node * 32 + lane] = row;
    } else {
        row.x = fmaxf(row.x, 0.f); row.y = fmaxf(row.y, 0.f);
        row.z = fmaxf(row.z, 0.f); row.w = fmaxf(row.w, 0.f);
        float4 w0 = swf[lane * 4 + 0];
        float4 w1 = swf[lane * 4 + 1];
        float4 w2 = swf[lane * 4 + 2];
        float4 w3 = swf[lane * 4 + 3];
        float a0 = row.x * w0.x + row.y * w1.x + row.z * w2.x + row.w * w3.x;
        float a1 = row.x * w0.y + row.y * w1.y + row.z * w2.y + row.w * w3.y;
        float a2 = row.x * w0.z + row.y * w1.z + row.z * w2.z + row.w * w3.z;
#pragma unroll
        for (int m = 16; m > 0; m >>= 1) {
            a0 += __shfl_xor_sync(0xffffffff, a0, m);
            a1 += __shfl_xor_sync(0xffffffff, a1, m);
            a2 += __shfl_xor_sync(0xffffffff, a2, m);
        }
        if (lane == 0)
            g_z[node] = make_float4(a0 * s, a1 * s, a2 * s, 0.f);
    }
}

// ---------------------------------------------------------------------------
// gather3: zagg[i] = dinv[i] * (z[i] + sum_in z[src])
// ---------------------------------------------------------------------------
__global__ __launch_bounds__(256) void gather3_kernel(int n) {
    const int node = blockIdx.x * blockDim.x + threadIdx.x;
    if (node >= n) return;

    float4 zv = g_z[node];
    float a0 = zv.x, a1 = zv.y, a2 = zv.z;

    const int off = g_off[node];
    const int deg = g_off[node + 1] - off;
    const int* __restrict__ src = g_srcs + off;

    int j = 0;
    for (; j + 4 <= deg; j += 4) {
        float4 v0 = __ldg(&g_z[src[j + 0]]);
        float4 v1 = __ldg(&g_z[src[j + 1]]);
        float4 v2 = __ldg(&g_z[src[j + 2]]);
        float4 v3 = __ldg(&g_z[src[j + 3]]);
        a0 += (v0.x + v1.x) + (v2.x + v3.x);
        a1 += (v0.y + v1.y) + (v2.y + v3.y);
        a2 += (v0.z + v1.z) + (v2.z + v3.z);
    }
    for (; j < deg; j++) {
        float4 v = __ldg(&g_z[src[j]]);
        a0 += v.x; a1 += v.y; a2 += v.z;
    }
    float s = g_dinv[node];
    g_zagg[node] = make_float4(a0 * s, a1 * s, a2 * s, 0.f);
}

// ---------------------------------------------------------------------------
// pool: out[g] = mean over batch-range of zagg + bfold   (1 warp per graph)
// ---------------------------------------------------------------------------
__global__ __launch_bounds__(32) void pool_kernel(const int* __restrict__ batch,
                                                  float* __restrict__ out, int n) {
    const int g = blockIdx.x;
    const int lane = threadIdx.x;

    int target = g + (lane & 1);
    int lo = 0, hi = n;
    while (lo < hi) {
        int m = (lo + hi) >> 1;
        if (batch[m] < target) lo = m + 1; else hi = m;
    }
    int start = __shfl_sync(0xffffffff, lo, 0);
    int end   = __shfl_sync(0xffffffff, lo, 1);

    float a0 = 0.f, a1 = 0.f, a2 = 0.f;
    for (int i = start + lane; i < end; i += 32) {
        float4 v = g_zagg[i];
        a0 += v.x; a1 += v.y; a2 += v.z;
    }
#pragma unroll
    for (int m = 16; m > 0; m >>= 1) {
        a0 += __shfl_xor_sync(0xffffffff, a0, m);
        a1 += __shfl_xor_sync(0xffffffff, a1, m);
        a2 += __shfl_xor_sync(0xffffffff, a2, m);
    }
    if (lane == 0) {
        float inv = 1.f / fmaxf((float)(end - start), 1.f);
        float4 bf = g_bfold;
        out[g * 3 + 0] = fmaf(a0, inv, bf.x);
        out[g * 3 + 1] = fmaf(a1, inv, bf.y);
        out[g * 3 + 2] = fmaf(a2, inv, bf.z);
    }
}

// ---------------------------------------------------------------------------
// launch: hist -> scan, then fork {fill, fold} || gemm1, join, rest sequential
// ---------------------------------------------------------------------------
extern "C" void kernel_launch(void* const* d_in, const int* in_sizes, int n_in,
                              void* d_out, int out_size) {
    const float* x     = (const float*)d_in[0];
    const int*   ei    = (const int*)  d_in[1];
    const int*   batch = (const int*)  d_in[2];
    const float* W1    = (const float*)d_in[3];
    const float* b1    = (const float*)d_in[4];
    const float* W2    = (const float*)d_in[5];
    const float* b2    = (const float*)d_in[6];
    const float* W3    = (const float*)d_in[7];
    const float* b3    = (const float*)d_in[8];
    const float* Wlin  = (const float*)d_in[9];
    const float* blin  = (const float*)d_in[10];
    float* out = (float*)d_out;

    const int n = in_sizes[0] / D;   // 50000
    const int E = in_sizes[1] / 2;   // 800000

    __nv_bfloat16* hwb_ptr;
    cudaGetSymbolAddress((void**)&hwb_ptr, g_hwb);
    float* agg_ptr;
    cudaGetSymbolAddress((void**)&agg_ptr, g_agg);

    const int gemm_blocks = (n + 63) / 64;
    const int gath_blocks = (n + 7) / 8;
    const int e4_blocks   = ((E + 3) / 4 + 255) / 256;

    // sequential prefix: hist -> scan (dinv ready for gemm1 epilogue)
    hist_kernel<<<e4_blocks, 256>>>(ei, E);
    scan_kernel<<<1, 1024>>>(n);

    // fork: side stream does fill + fold while main stream runs GEMM1
    cudaEventRecord(g_ev_fork, 0);
    cudaStreamWaitEvent(g_side_stream, g_ev_fork, 0);
    fill_kernel<<<e4_blocks, 256, 0, g_side_stream>>>(ei, E);
    fold_kernel<<<D + 1, 32, 0, g_side_stream>>>(W3, b3, Wlin, blin);
    cudaEventRecord(g_ev_join, g_side_stream);

    gemm_kernel<false><<<gemm_blocks, 128>>>(x, W1, hwb_ptr, n);

    cudaStreamWaitEvent(0, g_ev_join, 0);

    // layer 1 aggregation (bf16 gather -> fp32 agg)
    gather_kernel<false><<<gath_blocks, 256>>>(b1, n);

    // layer 2 + fused folded head
    gemm_kernel<true><<<gemm_blocks, 128>>>(agg_ptr, W2, hwb_ptr, n);
    gather_kernel<true><<<gath_blocks, 256>>>(b2, n);

    // layer 3 message passing on 3-wide features
    gather3_kernel<<<(n + 255) / 256, 256>>>(n);

    // mean pool + bias
    pool_kernel<<<N_GRAPHS, 32>>>(batch, out, n);
}

// round 13
// speedup vs baseline: 1.3763x; 1.1626x over previous
#include <cuda_runtime.h>
#include <cuda_bf16.h>

#define N_NODES  50000
#define N_EDGES  800000
#define N_GRAPHS 128
#define D        128

// Scratch (device globals — no allocation allowed)
__device__ __nv_bfloat16 g_hwb[N_NODES * D];  // (H @ W) * dinv[row], bf16
__device__ float g_agg[N_NODES * D];    // layer-1 aggregated output (fp32)
__device__ float4 g_z[N_NODES];         // folded layer-3 features (3 used)
__device__ float4 g_zagg[N_NODES];      // aggregated layer-3 output
__device__ float g_dinv[N_NODES];
__device__ int   g_ecnt[N_NODES];       // zero-init; re-zeroed by scan each replay
__device__ int   g_off[N_NODES + 1];    // CSR offsets
__device__ int   g_cur[N_NODES];        // fill cursors
__device__ int   g_srcs[N_EDGES];       // src node ids, grouped by dst
__device__ float4 g_wfold[D];           // W3 @ Wlin rows (xyz used)
__device__ float4 g_bfold;              // b3 @ Wlin + blin

// ---------------------------------------------------------------------------
// Streams/events for fork-join inside CUDA-graph capture (created once).
// ---------------------------------------------------------------------------
static cudaStream_t g_side_stream;
static cudaEvent_t  g_ev_fork, g_ev_join;
static struct StreamInit {
    StreamInit() {
        cudaStreamCreateWithFlags(&g_side_stream, cudaStreamNonBlocking);
        cudaEventCreateWithFlags(&g_ev_fork, cudaEventDisableTiming);
        cudaEventCreateWithFlags(&g_ev_join, cudaEventDisableTiming);
    }
} g_stream_init;

// ---------------------------------------------------------------------------
// helpers
// ---------------------------------------------------------------------------
__device__ __forceinline__ unsigned pack_bf16(float lo, float hi) {
    unsigned r;
    asm("cvt.rn.bf16x2.f32 %0, %1, %2;" : "=r"(r) : "f"(hi), "f"(lo));
    return r;
}
__device__ __forceinline__ float4 bf16x4_to_float4(uint2 w) {
    __nv_bfloat162 a = *reinterpret_cast<__nv_bfloat162*>(&w.x);
    __nv_bfloat162 b = *reinterpret_cast<__nv_bfloat162*>(&w.y);
    float2 fa = __bfloat1622float2(a);
    float2 fb = __bfloat1622float2(b);
    return make_float4(fa.x, fa.y, fb.x, fb.y);
}
__device__ __forceinline__ unsigned f2tf32(float f) {
    unsigned u;
    asm("cvt.rna.tf32.f32 %0, %1;" : "=r"(u) : "f"(f));
    return u;
}
__device__ __forceinline__ void mma_tf32(float* d, const unsigned* a,
                                         unsigned b0, unsigned b1) {
    asm volatile(
        "mma.sync.aligned.m16n8k8.row.col.f32.tf32.tf32.f32 "
        "{%0,%1,%2,%3}, {%4,%5,%6,%7}, {%8,%9}, {%0,%1,%2,%3};"
        : "+f"(d[0]), "+f"(d[1]), "+f"(d[2]), "+f"(d[3])
        : "r"(a[0]), "r"(a[1]), "r"(a[2]), "r"(a[3]), "r"(b0), "r"(b1));
}

// ---------------------------------------------------------------------------
// Fold W3@Wlin (+ b3@Wlin+blin): 129 blocks x 32 threads, shfl reduce.
// ---------------------------------------------------------------------------
__global__ __launch_bounds__(32) void fold_kernel(const float* __restrict__ W3,
                                                  const float* __restrict__ b3,
                                                  const float* __restrict__ Wlin,
                                                  const float* __restrict__ blin) {
    const int r    = blockIdx.x;     // 0..127 rows, 128 = bias
    const int lane = threadIdx.x;
    float a0 = 0.f, a1 = 0.f, a2 = 0.f;
    const float* vec = (r < D) ? (W3 + r * D) : b3;
#pragma unroll
    for (int k = lane; k < D; k += 32) {
        float w = vec[k];
        a0 = fmaf(w, Wlin[k * 3 + 0], a0);
        a1 = fmaf(w, Wlin[k * 3 + 1], a1);
        a2 = fmaf(w, Wlin[k * 3 + 2], a2);
    }
#pragma unroll
    for (int m = 16; m > 0; m >>= 1) {
        a0 += __shfl_xor_sync(0xffffffff, a0, m);
        a1 += __shfl_xor_sync(0xffffffff, a1, m);
        a2 += __shfl_xor_sync(0xffffffff, a2, m);
    }
    if (lane == 0) {
        if (r < D) g_wfold[r] = make_float4(a0, a1, a2, 0.f);
        else       g_bfold   = make_float4(a0 + blin[0], a1 + blin[1], a2 + blin[2], 0.f);
    }
}

// ---------------------------------------------------------------------------
// CSR build: histogram (int4) -> scan (+dinv, +self-reset) -> fill (int4)
// ---------------------------------------------------------------------------
__global__ void hist_kernel(const int* __restrict__ ei, int E) {
    int e = (blockIdx.x * blockDim.x + threadIdx.x) * 4;
    if (e + 3 < E) {
        int4 c = *(const int4*)(ei + E + e);
        atomicAdd(&g_ecnt[c.x], 1);
        atomicAdd(&g_ecnt[c.y], 1);
        atomicAdd(&g_ecnt[c.z], 1);
        atomicAdd(&g_ecnt[c.w], 1);
    } else {
        for (; e < E; e++) atomicAdd(&g_ecnt[ei[E + e]], 1);
    }
}

__global__ void scan_kernel(int n) {
    __shared__ int part[1024];
    const int t = threadIdx.x;
    const int chunk = (n + 1023) / 1024;
    const int s = t * chunk;
    const int e = min(s + chunk, n);
    int sum = 0;
    for (int i = s; i < e; i++) sum += g_ecnt[i];
    part[t] = sum;
    __syncthreads();
    for (int d = 1; d < 1024; d <<= 1) {
        int v = (t >= d) ? part[t - d] : 0;
        __syncthreads();
        part[t] += v;
        __syncthreads();
    }
    int run = part[t] - sum;
    for (int i = s; i < e; i++) {
        int c = g_ecnt[i];
        g_ecnt[i] = 0;                        // reset for next replay
        g_off[i] = run;
        g_cur[i] = run;
        g_dinv[i] = rsqrtf((float)(c + 1));   // +1 self-loop
        run += c;
    }
    if (e == n && s < n) g_off[n] = run;
}

__global__ void fill_kernel(const int* __restrict__ ei, int E) {
    int e = (blockIdx.x * blockDim.x + threadIdx.x) * 4;
    if (e + 3 < E) {
        int4 r = *(const int4*)(ei + e);
        int4 c = *(const int4*)(ei + E + e);
        g_srcs[atomicAdd(&g_cur[c.x], 1)] = r.x;
        g_srcs[atomicAdd(&g_cur[c.y], 1)] = r.y;
        g_srcs[atomicAdd(&g_cur[c.z], 1)] = r.z;
        g_srcs[atomicAdd(&g_cur[c.w], 1)] = r.w;
    } else {
        for (; e < E; e++)
            g_srcs[atomicAdd(&g_cur[ei[E + e]], 1)] = ei[e];
    }
}

// ---------------------------------------------------------------------------
// GEMM (tf32 tensor core): OUTB[r,:] = bf16( (act(H)[r,:] @ W) * dinv[r] )
// 128 threads (4 warps as 2x2), 64-row tiles, warp tile m32 x n64.
// mma.m16n8k8 tf32, fp32 accumulate. A smem stride 132, W stride 136
// (conflict-free for fragment access patterns). 50KB dynamic smem.
// ---------------------------------------------------------------------------
#define SA_STRIDE 132
#define SW_STRIDE 136
#define GEMM_SMEM ((64 * SA_STRIDE + 32 * SW_STRIDE) * 4)

template <bool RELU>
__global__ __launch_bounds__(128, 4) void gemm_kernel(const float* __restrict__ H,
                                                      const float* __restrict__ W,
                                                      __nv_bfloat16* __restrict__ OUTB,
                                                      int n) {
    extern __shared__ unsigned smem[];
    unsigned* sA = smem;                      // [64][SA_STRIDE] tf32
    unsigned* sW = smem + 64 * SA_STRIDE;     // [32][SW_STRIDE] tf32 (one k-chunk)

    const int tid  = threadIdx.x;
    const int row0 = blockIdx.x * 64;
    const int warp = tid >> 5;
    const int lane = tid & 31;
    const int g = lane >> 2;        // 0..7
    const int t = lane & 3;         // 0..3
    const int wr = warp >> 1;       // warp row 0..1
    const int wc = warp & 1;        // warp col 0..1
    const int rbase = wr * 32;      // rows within tile
    const int cbase = wc * 64;      // cols

    // stage A (64x128) -> tf32, optional ReLU
#pragma unroll
    for (int i = 0; i < 16; i++) {
        int idx = (i * 128 + tid) * 4;
        int r = idx >> 7, c = idx & 127;
        float4 v;
        if (row0 + r < n) {
            v = *(const float4*)(H + (row0 + r) * D + c);
            if (RELU) {
                v.x = fmaxf(v.x, 0.f); v.y = fmaxf(v.y, 0.f);
                v.z = fmaxf(v.z, 0.f); v.w = fmaxf(v.w, 0.f);
            }
        } else {
            v = make_float4(0.f, 0.f, 0.f, 0.f);
        }
        uint4 u;
        u.x = f2tf32(v.x); u.y = f2tf32(v.y);
        u.z = f2tf32(v.z); u.w = f2tf32(v.w);
        *(uint4*)(sA + r * SA_STRIDE + c) = u;
    }

    float acc[2][8][4] = {};   // [m-tile][n-tile][frag]

#pragma unroll
    for (int kc = 0; kc < 4; kc++) {
        __syncthreads();
        // stage W rows [kc*32, kc*32+32) -> tf32
#pragma unroll
        for (int i = 0; i < 8; i++) {
            int idx = (i * 128 + tid) * 4;
            int r = idx >> 7, c = idx & 127;
            float4 v = *(const float4*)(W + (kc * 32 + r) * D + c);
            uint4 u;
            u.x = f2tf32(v.x); u.y = f2tf32(v.y);
            u.z = f2tf32(v.z); u.w = f2tf32(v.w);
            *(uint4*)(sW + r * SW_STRIDE + c) = u;
        }
        __syncthreads();

#pragma unroll
        for (int k8 = 0; k8 < 32; k8 += 8) {
            const int kk = kc * 32 + k8;   // global k for A
            // A fragments: a0:(g,t) a1:(g+8,t) a2:(g,t+4) a3:(g+8,t+4)
            unsigned a[2][4];
#pragma unroll
            for (int mt = 0; mt < 2; mt++) {
                int ra = rbase + mt * 16 + g;
                a[mt][0] = sA[ra * SA_STRIDE + kk + t];
                a[mt][1] = sA[(ra + 8) * SA_STRIDE + kk + t];
                a[mt][2] = sA[ra * SA_STRIDE + kk + t + 4];
                a[mt][3] = sA[(ra + 8) * SA_STRIDE + kk + t + 4];
            }
#pragma unroll
            for (int nt = 0; nt < 8; nt++) {
                int col = cbase + nt * 8 + g;
                unsigned b0 = sW[(k8 + t) * SW_STRIDE + col];
                unsigned b1 = sW[(k8 + t + 4) * SW_STRIDE + col];
                mma_tf32(acc[0][nt], a[0], b0, b1);
                mma_tf32(acc[1][nt], a[1], b0, b1);
            }
        }
    }

    // epilogue: *dinv, bf16x2 packed stores
    unsigned* outp = (unsigned*)OUTB;   // 64 bf16x2 words per row
#pragma unroll
    for (int mt = 0; mt < 2; mt++) {
        int r1 = row0 + rbase + mt * 16 + g;
        int r2 = r1 + 8;
        float s1 = (r1 < n) ? g_dinv[r1] : 0.f;
        float s2 = (r2 < n) ? g_dinv[r2] : 0.f;
#pragma unroll
        for (int nt = 0; nt < 8; nt++) {
            int w = (cbase >> 1) + nt * 4 + t;   // bf16x2 word index in row
            if (r1 < n)
                outp[r1 * 64 + w] = pack_bf16(acc[mt][nt][0] * s1,
                                              acc[mt][nt][1] * s1);
            if (r2 < n)
                outp[r2 * 64 + w] = pack_bf16(acc[mt][nt][2] * s2,
                                              acc[mt][nt][3] * s2);
        }
    }
}

// ---------------------------------------------------------------------------
// Gather aggregation (warp per node, 4 bf16 per lane via LDG.64):
// row = dinv[i] * (hw'[i] + sum_in hw'[src]) + b    (accumulate fp32)
// FUSE_HEAD=false: write row to g_agg (fp32).
// FUSE_HEAD=true : relu(row) @ Wfold (smem) -> warp reduce -> g_z[i] *= dinv.
// ---------------------------------------------------------------------------
template <bool FUSE_HEAD>
__global__ __launch_bounds__(256) void gather_kernel(const float* __restrict__ b, int n) {
    __shared__ float4 swf[D];
    if (FUSE_HEAD) {
        if (threadIdx.x < D) swf[threadIdx.x] = g_wfold[threadIdx.x];
        __syncthreads();
    }

    const int node = blockIdx.x * 8 + (threadIdx.x >> 5);
    const int lane = threadIdx.x & 31;
    if (node >= n) return;

    const uint2* __restrict__ hwb = (const uint2*)g_hwb;   // 32 uint2 per row
    float4 acc = bf16x4_to_float4(hwb[node * 32 + lane]);  // self term

    const int off = g_off[node];
    const int deg = g_off[node + 1] - off;
    const int* __restrict__ src = g_srcs + off;

    int j = 0;
    for (; j + 8 <= deg; j += 8) {
        uint2 w0 = __ldg(hwb + src[j + 0] * 32 + lane);
        uint2 w1 = __ldg(hwb + src[j + 1] * 32 + lane);
        uint2 w2 = __ldg(hwb + src[j + 2] * 32 + lane);
        uint2 w3 = __ldg(hwb + src[j + 3] * 32 + lane);
        uint2 w4 = __ldg(hwb + src[j + 4] * 32 + lane);
        uint2 w5 = __ldg(hwb + src[j + 5] * 32 + lane);
        uint2 w6 = __ldg(hwb + src[j + 6] * 32 + lane);
        uint2 w7 = __ldg(hwb + src[j + 7] * 32 + lane);
        float4 v0 = bf16x4_to_float4(w0);
        float4 v1 = bf16x4_to_float4(w1);
        float4 v2 = bf16x4_to_float4(w2);
        float4 v3 = bf16x4_to_float4(w3);
        float4 v4 = bf16x4_to_float4(w4);
        float4 v5 = bf16x4_to_float4(w5);
        float4 v6 = bf16x4_to_float4(w6);
        float4 v7 = bf16x4_to_float4(w7);
        acc.x += (v0.x + v1.x) + (v2.x + v3.x) + ((v4.x + v5.x) + (v6.x + v7.x));
        acc.y += (v0.y + v1.y) + (v2.y + v3.y) + ((v4.y + v5.y) + (v6.y + v7.y));
        acc.z += (v0.z + v1.z) + (v2.z + v3.z) + ((v4.z + v5.z) + (v6.z + v7.z));
        acc.w += (v0.w + v1.w) + (v2.w + v3.w) + ((v4.w + v5.w) + (v6.w + v7.w));
    }
    for (; j + 4 <= deg; j += 4) {
        uint2 w0 = __ldg(hwb + src[j + 0] * 32 + lane);
        uint2 w1 = __ldg(hwb + src[j + 1] * 32 + lane);
        uint2 w2 = __ldg(hwb + src[j + 2] * 32 + lane);
        uint2 w3 = __ldg(hwb + src[j + 3] * 32 + lane);
        float4 v0 = bf16x4_to_float4(w0);
        float4 v1 = bf16x4_to_float4(w1);
        float4 v2 = bf16x4_to_float4(w2);
        float4 v3 = bf16x4_to_float4(w3);
        acc.x += (v0.x + v1.x) + (v2.x + v3.x);
        acc.y += (v0.y + v1.y) + (v2.y + v3.y);
        acc.z += (v0.z + v1.z) + (v2.z + v3.z);
        acc.w += (v0.w + v1.w) + (v2.w + v3.w);
    }
    for (; j < deg; j++) {
        float4 v = bf16x4_to_float4(__ldg(hwb + src[j] * 32 + lane));
        acc.x += v.x; acc.y += v.y; acc.z += v.z; acc.w += v.w;
    }

    float s = g_dinv[node];
    float4 bb = ((const float4*)b)[lane];
    float4 row;
    row.x = fmaf(acc.x, s, bb.x);
    row.y = fmaf(acc.y, s, bb.y);
    row.z = fmaf(acc.z, s, bb.z);
    row.w = fmaf(acc.w, s, bb.w);

    if (!FUSE_HEAD) {
        ((float4*)g_agg)[node * 32 + lane] = row;
    } else {
        row.x = fmaxf(row.x, 0.f); row.y = fmaxf(row.y, 0.f);
        row.z = fmaxf(row.z, 0.f); row.w = fmaxf(row.w, 0.f);
        float4 w0 = swf[lane * 4 + 0];
        float4 w1 = swf[lane * 4 + 1];
        float4 w2 = swf[lane * 4 + 2];
        float4 w3 = swf[lane * 4 + 3];
        float a0 = row.x * w0.x + row.y * w1.x + row.z * w2.x + row.w * w3.x;
        float a1 = row.x * w0.y + row.y * w1.y + row.z * w2.y + row.w * w3.y;
        float a2 = row.x * w0.z + row.y * w1.z + row.z * w2.z + row.w * w3.z;
#pragma unroll
        for (int m = 16; m > 0; m >>= 1) {
            a0 += __shfl_xor_sync(0xffffffff, a0, m);
            a1 += __shfl_xor_sync(0xffffffff, a1, m);
            a2 += __shfl_xor_sync(0xffffffff, a2, m);
        }
        if (lane == 0)
            g_z[node] = make_float4(a0 * s, a1 * s, a2 * s, 0.f);
    }
}

// ---------------------------------------------------------------------------
// gather3: zagg[i] = dinv[i] * (z[i] + sum_in z[src])
// ---------------------------------------------------------------------------
__global__ __launch_bounds__(256) void gather3_kernel(int n) {
    const int node = blockIdx.x * blockDim.x + threadIdx.x;
    if (node >= n) return;

    float4 zv = g_z[node];
    float a0 = zv.x, a1 = zv.y, a2 = zv.z;

    const int off = g_off[node];
    const int deg = g_off[node + 1] - off;
    const int* __restrict__ src = g_srcs + off;

    int j = 0;
    for (; j + 4 <= deg; j += 4) {
        float4 v0 = __ldg(&g_z[src[j + 0]]);
        float4 v1 = __ldg(&g_z[src[j + 1]]);
        float4 v2 = __ldg(&g_z[src[j + 2]]);
        float4 v3 = __ldg(&g_z[src[j + 3]]);
        a0 += (v0.x + v1.x) + (v2.x + v3.x);
        a1 += (v0.y + v1.y) + (v2.y + v3.y);
        a2 += (v0.z + v1.z) + (v2.z + v3.z);
    }
    for (; j < deg; j++) {
        float4 v = __ldg(&g_z[src[j]]);
        a0 += v.x; a1 += v.y; a2 += v.z;
    }
    float s = g_dinv[node];
    g_zagg[node] = make_float4(a0 * s, a1 * s, a2 * s, 0.f);
}

// ---------------------------------------------------------------------------
// pool: out[g] = mean over batch-range of zagg + bfold   (1 warp per graph)
// ---------------------------------------------------------------------------
__global__ __launch_bounds__(32) void pool_kernel(const int* __restrict__ batch,
                                                  float* __restrict__ out, int n) {
    const int g = blockIdx.x;
    const int lane = threadIdx.x;

    int target = g + (lane & 1);
    int lo = 0, hi = n;
    while (lo < hi) {
        int m = (lo + hi) >> 1;
        if (batch[m] < target) lo = m + 1; else hi = m;
    }
    int start = __shfl_sync(0xffffffff, lo, 0);
    int end   = __shfl_sync(0xffffffff, lo, 1);

    float a0 = 0.f, a1 = 0.f, a2 = 0.f;
    for (int i = start + lane; i < end; i += 32) {
        float4 v = g_zagg[i];
        a0 += v.x; a1 += v.y; a2 += v.z;
    }
#pragma unroll
    for (int m = 16; m > 0; m >>= 1) {
        a0 += __shfl_xor_sync(0xffffffff, a0, m);
        a1 += __shfl_xor_sync(0xffffffff, a1, m);
        a2 += __shfl_xor_sync(0xffffffff, a2, m);
    }
    if (lane == 0) {
        float inv = 1.f / fmaxf((float)(end - start), 1.f);
        float4 bf = g_bfold;
        out[g * 3 + 0] = fmaf(a0, inv, bf.x);
        out[g * 3 + 1] = fmaf(a1, inv, bf.y);
        out[g * 3 + 2] = fmaf(a2, inv, bf.z);
    }
}

// ---------------------------------------------------------------------------
// launch: hist -> scan, then fork {fill, fold} || gemm1, join, rest sequential
// ---------------------------------------------------------------------------
extern "C" void kernel_launch(void* const* d_in, const int* in_sizes, int n_in,
                              void* d_out, int out_size) {
    const float* x     = (const float*)d_in[0];
    const int*   ei    = (const int*)  d_in[1];
    const int*   batch = (const int*)  d_in[2];
    const float* W1    = (const float*)d_in[3];
    const float* b1    = (const float*)d_in[4];
    const float* W2    = (const float*)d_in[5];
    const float* b2    = (const float*)d_in[6];
    const float* W3    = (const float*)d_in[7];
    const float* b3    = (const float*)d_in[8];
    const float* Wlin  = (const float*)d_in[9];
    const float* blin  = (const float*)d_in[10];
    float* out = (float*)d_out;

    const int n = in_sizes[0] / D;   // 50000
    const int E = in_sizes[1] / 2;   // 800000

    __nv_bfloat16* hwb_ptr;
    cudaGetSymbolAddress((void**)&hwb_ptr, g_hwb);
    float* agg_ptr;
    cudaGetSymbolAddress((void**)&agg_ptr, g_agg);

    cudaFuncSetAttribute(gemm_kernel<false>,
                         cudaFuncAttributeMaxDynamicSharedMemorySize, GEMM_SMEM);
    cudaFuncSetAttribute(gemm_kernel<true>,
                         cudaFuncAttributeMaxDynamicSharedMemorySize, GEMM_SMEM);

    const int gemm_blocks = (n + 63) / 64;
    const int gath_blocks = (n + 7) / 8;
    const int e4_blocks   = ((E + 3) / 4 + 255) / 256;

    // sequential prefix: hist -> scan (dinv ready for gemm1 epilogue)
    hist_kernel<<<e4_blocks, 256>>>(ei, E);
    scan_kernel<<<1, 1024>>>(n);

    // fork: side stream does fill + fold while main stream runs GEMM1
    cudaEventRecord(g_ev_fork, 0);
    cudaStreamWaitEvent(g_side_stream, g_ev_fork, 0);
    fill_kernel<<<e4_blocks, 256, 0, g_side_stream>>>(ei, E);
    fold_kernel<<<D + 1, 32, 0, g_side_stream>>>(W3, b3, Wlin, blin);
    cudaEventRecord(g_ev_join, g_side_stream);

    gemm_kernel<false><<<gemm_blocks, 128, GEMM_SMEM>>>(x, W1, hwb_ptr, n);

    cudaStreamWaitEvent(0, g_ev_join, 0);

    // layer 1 aggregation (bf16 gather -> fp32 agg)
    gather_kernel<false><<<gath_blocks, 256>>>(b1, n);

    // layer 2 + fused folded head
    gemm_kernel<true><<<gemm_blocks, 128, GEMM_SMEM>>>(agg_ptr, W2, hwb_ptr, n);
    gather_kernel<true><<<gath_blocks, 256>>>(b2, n);

    // layer 3 message passing on 3-wide features
    gather3_kernel<<<(n + 255) / 256, 256>>>(n);

    // mean pool + bias
    pool_kernel<<<N_GRAPHS, 32>>>(batch, out, n);
}